// round 1
// baseline (speedup 1.0000x reference)
#include <cuda_runtime.h>

#define S_LEN 2048
#define DMODEL 1024
#define NHEADS 16
#define DK 64
#define BATCH 2
#define BH (BATCH * NHEADS)
#define MROWS (BATCH * S_LEN)   // 4096

// ---------------- scratch (device globals; no allocation allowed) ----------
__device__ float g_qh[BH * S_LEN * DK];   // (B,H,S,Dk) head-split
__device__ float g_kh[BH * S_LEN * DK];
__device__ float g_vh[BH * S_LEN * DK];
__device__ float g_ctx[BH * S_LEN * DK];
__device__ float g_m[BH * S_LEN];
__device__ float g_l[BH * S_LEN];

// ==========================================================================
// Tiled fp32 GEMM: C[M,1024] = A[M,1024] @ W[1024,1024] + bias
// BM=BN=128, BK=16, 256 threads, 8x8 per-thread microtile.
// SPLIT_IN : A is read from head-split layout (B,H,S,Dk) as merged (m, h*64+d)
// SPLIT_OUT: C is written to head-split layout (B,H,S,Dk)
// ==========================================================================
template <bool SPLIT_IN, bool SPLIT_OUT>
__global__ __launch_bounds__(256) void gemm128(
    const float* __restrict__ A, const float* __restrict__ W,
    const float* __restrict__ bias, float* __restrict__ C)
{
    __shared__ float As[16 * 132];
    __shared__ float Bs[16 * 132];

    const int tid = threadIdx.x;
    const int m0 = blockIdx.y * 128;
    const int n0 = blockIdx.x * 128;
    const int tx = tid & 15;   // n direction
    const int ty = tid >> 4;   // m direction

    float acc[8][8];
#pragma unroll
    for (int i = 0; i < 8; i++)
#pragma unroll
        for (int j = 0; j < 8; j++) acc[i][j] = 0.f;

    for (int kt = 0; kt < 64; kt++) {
        // ---- load A tile (128 rows x 16 k) ----
#pragma unroll
        for (int li = 0; li < 2; li++) {
            int lin = tid + li * 256;
            int r = lin >> 2;            // 0..127
            int c4 = (lin & 3) << 2;     // 0,4,8,12
            const float* ap;
            if (!SPLIT_IN) {
                ap = &A[(size_t)(m0 + r) * 1024 + kt * 16 + c4];
            } else {
                int m = m0 + r;
                int b = m >> 11, s = m & 2047;
                int k = kt * 16 + c4;
                int h = k >> 6, d = k & 63;
                ap = &A[(((size_t)(b * 16 + h)) * S_LEN + s) * DK + d];
            }
            float4 v = *(const float4*)ap;
            As[(c4 + 0) * 132 + r] = v.x;
            As[(c4 + 1) * 132 + r] = v.y;
            As[(c4 + 2) * 132 + r] = v.z;
            As[(c4 + 3) * 132 + r] = v.w;
        }
        // ---- load W tile (16 k x 128 n) ----
#pragma unroll
        for (int li = 0; li < 2; li++) {
            int lin = tid + li * 256;
            int r = lin >> 5;            // 0..15
            int c4 = (lin & 31) << 2;    // 0..124
            float4 v = *(const float4*)&W[(size_t)(kt * 16 + r) * 1024 + n0 + c4];
            *(float4*)&Bs[r * 132 + c4] = v;
        }
        __syncthreads();

#pragma unroll
        for (int kk = 0; kk < 16; kk++) {
            float a[8], b[8];
            *(float4*)&a[0] = *(const float4*)&As[kk * 132 + ty * 8];
            *(float4*)&a[4] = *(const float4*)&As[kk * 132 + ty * 8 + 4];
            *(float4*)&b[0] = *(const float4*)&Bs[kk * 132 + tx * 8];
            *(float4*)&b[4] = *(const float4*)&Bs[kk * 132 + tx * 8 + 4];
#pragma unroll
            for (int i = 0; i < 8; i++)
#pragma unroll
                for (int j = 0; j < 8; j++) acc[i][j] += a[i] * b[j];
        }
        __syncthreads();
    }

    // ---- bias + store ----
    float bv[8];
#pragma unroll
    for (int j = 0; j < 8; j++) bv[j] = bias[n0 + tx * 8 + j];

#pragma unroll
    for (int i = 0; i < 8; i++) {
        int m = m0 + ty * 8 + i;
        float4 o0, o1;
        o0.x = acc[i][0] + bv[0]; o0.y = acc[i][1] + bv[1];
        o0.z = acc[i][2] + bv[2]; o0.w = acc[i][3] + bv[3];
        o1.x = acc[i][4] + bv[4]; o1.y = acc[i][5] + bv[5];
        o1.z = acc[i][6] + bv[6]; o1.w = acc[i][7] + bv[7];
        if (!SPLIT_OUT) {
            float* cp = &C[(size_t)m * 1024 + n0 + tx * 8];
            *(float4*)cp = o0;
            *(float4*)(cp + 4) = o1;
        } else {
            int b = m >> 11, s = m & 2047;
            int n = n0 + tx * 8;
            int h = n >> 6, d = n & 63;
            float* cp = &C[(((size_t)(b * 16 + h)) * S_LEN + s) * DK + d];
            *(float4*)cp = o0;
            *(float4*)(cp + 4) = o1;
        }
    }
}

// ==========================================================================
// Attention pass 1: per-query-row running max m and sumexp l (causal).
// grid = (S/64, BH), block = 256. Thread (rg=tid>>4, cg=tid&15) owns a
// 4-row x 4-col microtile of the 64x64 score tile.
// ==========================================================================
__global__ __launch_bounds__(256) void attn_pass1(
    const float* __restrict__ qh, const float* __restrict__ kh,
    float* __restrict__ gm, float* __restrict__ gl)
{
    extern __shared__ float smem[];
    float* Qs = smem;            // 64*65
    float* Ks = smem + 64 * 65;  // 64*65

    const int tid = threadIdx.x;
    const int qt = blockIdx.x, bh = blockIdx.y;
    const size_t base = (size_t)bh * (S_LEN * DK);
    const int i0 = qt * 64;
    const int rg = tid >> 4, cg = tid & 15;

    // load Q tile
#pragma unroll
    for (int li = 0; li < 4; li++) {
        int idx4 = tid + li * 256;
        int r = idx4 >> 4, c = (idx4 & 15) << 2;
        float4 v = *(const float4*)&qh[base + (size_t)(i0 + r) * DK + c];
        Qs[r * 65 + c] = v.x; Qs[r * 65 + c + 1] = v.y;
        Qs[r * 65 + c + 2] = v.z; Qs[r * 65 + c + 3] = v.w;
    }

    float mrun[4], lrun[4];
#pragma unroll
    for (int ii = 0; ii < 4; ii++) { mrun[ii] = -1e30f; lrun[ii] = 0.f; }

    for (int jt = 0; jt <= qt; jt++) {
        __syncthreads();
#pragma unroll
        for (int li = 0; li < 4; li++) {
            int idx4 = tid + li * 256;
            int r = idx4 >> 4, c = (idx4 & 15) << 2;
            float4 v = *(const float4*)&kh[base + (size_t)(jt * 64 + r) * DK + c];
            Ks[r * 65 + c] = v.x; Ks[r * 65 + c + 1] = v.y;
            Ks[r * 65 + c + 2] = v.z; Ks[r * 65 + c + 3] = v.w;
        }
        __syncthreads();

        float s[4][4];
#pragma unroll
        for (int ii = 0; ii < 4; ii++)
#pragma unroll
            for (int jj = 0; jj < 4; jj++) s[ii][jj] = 0.f;

#pragma unroll 4
        for (int kk = 0; kk < 64; kk++) {
            float qv[4], kv[4];
#pragma unroll
            for (int ii = 0; ii < 4; ii++) qv[ii] = Qs[(rg * 4 + ii) * 65 + kk];
#pragma unroll
            for (int jj = 0; jj < 4; jj++) kv[jj] = Ks[(cg * 4 + jj) * 65 + kk];
#pragma unroll
            for (int ii = 0; ii < 4; ii++)
#pragma unroll
                for (int jj = 0; jj < 4; jj++) s[ii][jj] += qv[ii] * kv[jj];
        }

        const bool diag = (jt == qt);
#pragma unroll
        for (int ii = 0; ii < 4; ii++) {
            int gi = i0 + rg * 4 + ii;
            float mx = -1e30f;
#pragma unroll
            for (int jj = 0; jj < 4; jj++) {
                float sc = s[ii][jj] * 0.125f;
                if (diag && (jt * 64 + cg * 4 + jj) > gi) sc = -1e30f;
                s[ii][jj] = sc;
                mx = fmaxf(mx, sc);
            }
#pragma unroll
            for (int off = 1; off < 16; off <<= 1)
                mx = fmaxf(mx, __shfl_xor_sync(0xffffffffu, mx, off));
            float nm = fmaxf(mrun[ii], mx);
            float ts = 0.f;
#pragma unroll
            for (int jj = 0; jj < 4; jj++) ts += __expf(s[ii][jj] - nm);
#pragma unroll
            for (int off = 1; off < 16; off <<= 1)
                ts += __shfl_xor_sync(0xffffffffu, ts, off);
            lrun[ii] = lrun[ii] * __expf(mrun[ii] - nm) + ts;
            mrun[ii] = nm;
        }
    }

    if (cg == 0) {
#pragma unroll
        for (int ii = 0; ii < 4; ii++) {
            int gi = i0 + rg * 4 + ii;
            gm[bh * S_LEN + gi] = mrun[ii];
            gl[bh * S_LEN + gi] = lrun[ii];
        }
    }
}

// ==========================================================================
// Attention pass 2: p = exp(s - m)/l, optionally write attn to gmem,
// accumulate ctx = P @ V. Same block decomposition as pass 1.
// ==========================================================================
__global__ __launch_bounds__(256) void attn_pass2(
    const float* __restrict__ qh, const float* __restrict__ kh,
    const float* __restrict__ vh,
    const float* __restrict__ gm, const float* __restrict__ gl,
    float* __restrict__ attn, float* __restrict__ ctx)
{
    extern __shared__ float smem[];
    float* Qs = smem;
    float* Ks = Qs + 64 * 65;
    float* Vs = Ks + 64 * 65;
    float* Ps = Vs + 64 * 65;

    const int tid = threadIdx.x;
    const int qt = blockIdx.x, bh = blockIdx.y;
    const size_t base = (size_t)bh * (S_LEN * DK);
    const int i0 = qt * 64;
    const int rg = tid >> 4, cg = tid & 15;

#pragma unroll
    for (int li = 0; li < 4; li++) {
        int idx4 = tid + li * 256;
        int r = idx4 >> 4, c = (idx4 & 15) << 2;
        float4 v = *(const float4*)&qh[base + (size_t)(i0 + r) * DK + c];
        Qs[r * 65 + c] = v.x; Qs[r * 65 + c + 1] = v.y;
        Qs[r * 65 + c + 2] = v.z; Qs[r * 65 + c + 3] = v.w;
    }

    float mv[4], linv[4];
#pragma unroll
    for (int ii = 0; ii < 4; ii++) {
        int gi = i0 + rg * 4 + ii;
        mv[ii] = gm[bh * S_LEN + gi];
        linv[ii] = 1.f / gl[bh * S_LEN + gi];
    }

    float acc[4][4];
#pragma unroll
    for (int ii = 0; ii < 4; ii++)
#pragma unroll
        for (int jj = 0; jj < 4; jj++) acc[ii][jj] = 0.f;

    for (int jt = 0; jt <= qt; jt++) {
        __syncthreads();
#pragma unroll
        for (int li = 0; li < 4; li++) {
            int idx4 = tid + li * 256;
            int r = idx4 >> 4, c = (idx4 & 15) << 2;
            float4 kv = *(const float4*)&kh[base + (size_t)(jt * 64 + r) * DK + c];
            Ks[r * 65 + c] = kv.x; Ks[r * 65 + c + 1] = kv.y;
            Ks[r * 65 + c + 2] = kv.z; Ks[r * 65 + c + 3] = kv.w;
            float4 vv = *(const float4*)&vh[base + (size_t)(jt * 64 + r) * DK + c];
            Vs[r * 65 + c] = vv.x; Vs[r * 65 + c + 1] = vv.y;
            Vs[r * 65 + c + 2] = vv.z; Vs[r * 65 + c + 3] = vv.w;
        }
        __syncthreads();

        float s[4][4];
#pragma unroll
        for (int ii = 0; ii < 4; ii++)
#pragma unroll
            for (int jj = 0; jj < 4; jj++) s[ii][jj] = 0.f;

#pragma unroll 4
        for (int kk = 0; kk < 64; kk++) {
            float qv[4], kv[4];
#pragma unroll
            for (int ii = 0; ii < 4; ii++) qv[ii] = Qs[(rg * 4 + ii) * 65 + kk];
#pragma unroll
            for (int jj = 0; jj < 4; jj++) kv[jj] = Ks[(cg * 4 + jj) * 65 + kk];
#pragma unroll
            for (int ii = 0; ii < 4; ii++)
#pragma unroll
                for (int jj = 0; jj < 4; jj++) s[ii][jj] += qv[ii] * kv[jj];
        }

        const bool diag = (jt == qt);
        float p[4][4];
#pragma unroll
        for (int ii = 0; ii < 4; ii++) {
            int gi = i0 + rg * 4 + ii;
#pragma unroll
            for (int jj = 0; jj < 4; jj++) {
                float pv;
                if (diag && (jt * 64 + cg * 4 + jj) > gi) pv = 0.f;
                else pv = __expf(s[ii][jj] * 0.125f - mv[ii]) * linv[ii];
                p[ii][jj] = pv;
                Ps[(rg * 4 + ii) * 65 + cg * 4 + jj] = pv;
            }
        }
        if (attn) {
#pragma unroll
            for (int ii = 0; ii < 4; ii++) {
                size_t aoff = ((size_t)bh * S_LEN + (size_t)(i0 + rg * 4 + ii)) * S_LEN
                              + jt * 64 + cg * 4;
                *(float4*)&attn[aoff] = make_float4(p[ii][0], p[ii][1], p[ii][2], p[ii][3]);
            }
        }
        __syncthreads();

#pragma unroll 4
        for (int j = 0; j < 64; j++) {
            float pr[4], vv[4];
#pragma unroll
            for (int ii = 0; ii < 4; ii++) pr[ii] = Ps[(rg * 4 + ii) * 65 + j];
#pragma unroll
            for (int jj = 0; jj < 4; jj++) vv[jj] = Vs[j * 65 + cg * 4 + jj];
#pragma unroll
            for (int ii = 0; ii < 4; ii++)
#pragma unroll
                for (int jj = 0; jj < 4; jj++) acc[ii][jj] += pr[ii] * vv[jj];
        }
    }

#pragma unroll
    for (int ii = 0; ii < 4; ii++) {
        size_t coff = base + (size_t)(i0 + rg * 4 + ii) * DK + cg * 4;
        *(float4*)&ctx[coff] = make_float4(acc[ii][0], acc[ii][1], acc[ii][2], acc[ii][3]);
    }
}

// ==========================================================================
// host launch
// ==========================================================================
extern "C" void kernel_launch(void* const* d_in, const int* in_sizes, int n_in,
                              void* d_out, int out_size)
{
    const float* q  = (const float*)d_in[0];
    const float* k  = (const float*)d_in[1];
    const float* v  = (const float*)d_in[2];
    // d_in[3] = mask (causal tril; structure exploited directly)
    const float* wq = (const float*)d_in[4];
    const float* bq = (const float*)d_in[5];
    const float* wk = (const float*)d_in[6];
    const float* bk = (const float*)d_in[7];
    const float* wv = (const float*)d_in[8];
    const float* bv = (const float*)d_in[9];
    const float* wo = (const float*)d_in[10];
    const float* bo = (const float*)d_in[11];

    float *qh, *kh, *vh, *ctx, *gm, *gl;
    cudaGetSymbolAddress((void**)&qh, g_qh);
    cudaGetSymbolAddress((void**)&kh, g_kh);
    cudaGetSymbolAddress((void**)&vh, g_vh);
    cudaGetSymbolAddress((void**)&ctx, g_ctx);
    cudaGetSymbolAddress((void**)&gm, g_m);
    cudaGetSymbolAddress((void**)&gl, g_l);

    float* outbuf = (float*)d_out;
    float* out_ptr = nullptr;
    float* attn_ptr = nullptr;
    const long long OUT_N  = (long long)BATCH * S_LEN * DMODEL;        // 4,194,304
    const long long ATTN_N = (long long)BH * S_LEN * S_LEN;            // 134,217,728
    long long osz = (long long)out_size;
    if (osz >= OUT_N + ATTN_N)      { out_ptr = outbuf; attn_ptr = outbuf + OUT_N; }
    else if (osz == OUT_N)          { out_ptr = outbuf; }
    else                            { attn_ptr = outbuf; }

    // dynamic smem opt-in for pass2 (66,560 B > 48 KB default)
    static_assert(4 * 64 * 65 * 4 == 66560, "smem size");
    cudaFuncSetAttribute(attn_pass2, cudaFuncAttributeMaxDynamicSharedMemorySize, 66560);

    dim3 ggrid(DMODEL / 128, MROWS / 128);  // (8, 32)
    gemm128<false, true><<<ggrid, 256>>>(q, wq, bq, qh);
    gemm128<false, true><<<ggrid, 256>>>(k, wk, bk, kh);
    gemm128<false, true><<<ggrid, 256>>>(v, wv, bv, vh);

    dim3 agrid(S_LEN / 64, BH);             // (32, 32)
    attn_pass1<<<agrid, 256, 2 * 64 * 65 * 4>>>(qh, kh, gm, gl);

    if (attn_ptr) {
        cudaMemsetAsync(attn_ptr, 0, (size_t)ATTN_N * sizeof(float));
    }
    attn_pass2<<<agrid, 256, 66560>>>(qh, kh, vh, gm, gl, attn_ptr, ctx);

    if (out_ptr) {
        gemm128<true, false><<<ggrid, 256>>>(ctx, wo, bo, out_ptr);
    }
}

// round 2
// speedup vs baseline: 1.2938x; 1.2938x over previous
#include <cuda_runtime.h>

typedef unsigned long long ull;

#define S_LEN 2048
#define DMODEL 1024
#define NHEADS 16
#define DK 64
#define BATCH 2
#define BH (BATCH * NHEADS)
#define MROWS (BATCH * S_LEN)   // 4096
#define NTILE 32                // 2048/64 key tiles per row

// ---------------- scratch (device globals; no allocation allowed) ----------
__device__ float g_qh[BH * S_LEN * DK];   // (B,H,S,Dk) head-split
__device__ float g_kh[BH * S_LEN * DK];
__device__ float g_vh[BH * S_LEN * DK];
__device__ float g_ctx[BH * S_LEN * DK];
__device__ float g_m[BH * S_LEN];
__device__ float g_l[BH * S_LEN];
__device__ float g_snap[BH * NTILE * S_LEN];  // running max after each key tile

// ---------------- packed f32x2 helpers (FFMA2 path on sm_103a) -------------
__device__ __forceinline__ ull pack2(float x, float y) {
    ull r; asm("mov.b64 %0, {%1, %2};" : "=l"(r) : "f"(x), "f"(y)); return r;
}
__device__ __forceinline__ void unpack2(ull v, float& x, float& y) {
    asm("mov.b64 {%0, %1}, %2;" : "=f"(x), "=f"(y) : "l"(v));
}
__device__ __forceinline__ void fma2(ull& d, ull a, ull b) {
    asm("fma.rn.f32x2 %0, %1, %2, %0;" : "+l"(d) : "l"(a), "l"(b));
}
__device__ __forceinline__ void mul2(ull& d, ull a, ull b) {
    asm("mul.rn.f32x2 %0, %1, %2;" : "=l"(d) : "l"(a), "l"(b));
}

// ==========================================================================
// Tiled fp32 GEMM with FFMA2: C[M,1024] = A[M,1024] @ W[1024,1024] + bias
// BM=BN=128, BK=16, 256 threads, 8x8 per-thread microtile (packed pairs in n)
// ==========================================================================
template <bool SPLIT_IN, bool SPLIT_OUT>
__global__ __launch_bounds__(256) void gemm128(
    const float* __restrict__ A, const float* __restrict__ W,
    const float* __restrict__ bias, float* __restrict__ C)
{
    __shared__ float As[16 * 132];
    __shared__ float Bs[16 * 132];

    const int tid = threadIdx.x;
    const int m0 = blockIdx.y * 128;
    const int n0 = blockIdx.x * 128;
    const int tx = tid & 15;   // n direction
    const int ty = tid >> 4;   // m direction

    ull acc[8][4];             // [i][n-pair]
#pragma unroll
    for (int i = 0; i < 8; i++)
#pragma unroll
        for (int j = 0; j < 4; j++) acc[i][j] = 0ULL;

    for (int kt = 0; kt < 64; kt++) {
        // ---- load A tile (128 rows x 16 k), store transposed [k][m] ----
#pragma unroll
        for (int li = 0; li < 2; li++) {
            int lin = tid + li * 256;
            int r = lin >> 2;            // 0..127
            int c4 = (lin & 3) << 2;     // 0,4,8,12
            const float* ap;
            if (!SPLIT_IN) {
                ap = &A[(size_t)(m0 + r) * 1024 + kt * 16 + c4];
            } else {
                int m = m0 + r;
                int b = m >> 11, s = m & 2047;
                int k = kt * 16 + c4;
                int h = k >> 6, d = k & 63;
                ap = &A[(((size_t)(b * 16 + h)) * S_LEN + s) * DK + d];
            }
            float4 v = *(const float4*)ap;
            As[(c4 + 0) * 132 + r] = v.x;
            As[(c4 + 1) * 132 + r] = v.y;
            As[(c4 + 2) * 132 + r] = v.z;
            As[(c4 + 3) * 132 + r] = v.w;
        }
        // ---- load W tile (16 k x 128 n) ----
#pragma unroll
        for (int li = 0; li < 2; li++) {
            int lin = tid + li * 256;
            int r = lin >> 5;            // 0..15
            int c4 = (lin & 31) << 2;    // 0..124
            float4 v = *(const float4*)&W[(size_t)(kt * 16 + r) * 1024 + n0 + c4];
            *(float4*)&Bs[r * 132 + c4] = v;
        }
        __syncthreads();

#pragma unroll
        for (int kk = 0; kk < 16; kk++) {
            float a[8];
            *(float4*)&a[0] = *(const float4*)&As[kk * 132 + ty * 8];
            *(float4*)&a[4] = *(const float4*)&As[kk * 132 + ty * 8 + 4];
            union { float4 f; ull u[2]; } b0, b1;
            b0.f = *(const float4*)&Bs[kk * 132 + tx * 8];
            b1.f = *(const float4*)&Bs[kk * 132 + tx * 8 + 4];
#pragma unroll
            for (int i = 0; i < 8; i++) {
                ull ap = pack2(a[i], a[i]);
                fma2(acc[i][0], ap, b0.u[0]);
                fma2(acc[i][1], ap, b0.u[1]);
                fma2(acc[i][2], ap, b1.u[0]);
                fma2(acc[i][3], ap, b1.u[1]);
            }
        }
        __syncthreads();
    }

    // ---- bias + store ----
    float bv[8];
#pragma unroll
    for (int j = 0; j < 8; j++) bv[j] = bias[n0 + tx * 8 + j];

#pragma unroll
    for (int i = 0; i < 8; i++) {
        int m = m0 + ty * 8 + i;
        float o[8];
#pragma unroll
        for (int j = 0; j < 4; j++) unpack2(acc[i][j], o[2 * j], o[2 * j + 1]);
        float4 o0 = make_float4(o[0] + bv[0], o[1] + bv[1], o[2] + bv[2], o[3] + bv[3]);
        float4 o1 = make_float4(o[4] + bv[4], o[5] + bv[5], o[6] + bv[6], o[7] + bv[7]);
        if (!SPLIT_OUT) {
            float* cp = &C[(size_t)m * 1024 + n0 + tx * 8];
            *(float4*)cp = o0;
            *(float4*)(cp + 4) = o1;
        } else {
            int b = m >> 11, s = m & 2047;
            int n = n0 + tx * 8;
            int h = n >> 6, d = n & 63;
            float* cp = &C[(((size_t)(b * 16 + h)) * S_LEN + s) * DK + d];
            *(float4*)cp = o0;
            *(float4*)(cp + 4) = o1;
        }
    }
}

// ==========================================================================
// Fused single-pass causal attention.
// Tile: 128 queries x 64 keys. 256 threads, microtile 8 rows x 4 cols.
// Writes UNNORMALIZED p~ = exp(s - m_running) to attn buffer, snapshots the
// running max per (row, key-tile), accumulates ctx online (flash-style).
// grid = (BH, S/128)
// ==========================================================================
__global__ __launch_bounds__(256) void attn_fused(
    const float* __restrict__ qh, const float* __restrict__ kh,
    const float* __restrict__ vh,
    float* __restrict__ attn, float* __restrict__ ctx,
    float* __restrict__ gm, float* __restrict__ gl,
    float* __restrict__ gsnap)
{
    extern __shared__ float smf[];
    float* Qt = smf;               // [64][132]  Qt[d*132 + r], r=0..127
    float* Kt = Qt + 64 * 132;     // [64][68]   Kt[d*68 + j]
    float* Vs = Kt + 64 * 68;      // [64][68]   Vs[j*68 + d]
    float* Ps = Vs + 64 * 68;      // [128][68]  Ps[r*68 + j]

    const int tid = threadIdx.x;
    const int bh = blockIdx.x;
    const int qt = blockIdx.y;
    const size_t base = (size_t)bh * (S_LEN * DK);
    const int i0 = qt * 128;
    const int rg = tid >> 4, cg = tid & 15;
    const int row0 = rg * 8;

    // load Q tile transposed: Qt[d][r]
#pragma unroll
    for (int li = 0; li < 8; li++) {
        int lin = tid + li * 256;          // float4 index, 0..2047
        int r = lin >> 4, c4 = (lin & 15) << 2;
        float4 v = *(const float4*)&qh[base + (size_t)(i0 + r) * DK + c4];
        Qt[(c4 + 0) * 132 + r] = v.x;
        Qt[(c4 + 1) * 132 + r] = v.y;
        Qt[(c4 + 2) * 132 + r] = v.z;
        Qt[(c4 + 3) * 132 + r] = v.w;
    }

    float m[8], l[8];
    ull accpv[8][2];
#pragma unroll
    for (int ii = 0; ii < 8; ii++) {
        m[ii] = -1e30f; l[ii] = 0.f;
        accpv[ii][0] = 0ULL; accpv[ii][1] = 0ULL;
    }

    const int ntiles = 2 * qt + 2;
    for (int jt = 0; jt < ntiles; jt++) {
        const int j0 = jt * 64;
        __syncthreads();
        // load K tile transposed + V tile row-major
#pragma unroll
        for (int li = 0; li < 4; li++) {
            int lin = tid + li * 256;      // float4 index, 0..1023
            int r = lin >> 4, c4 = (lin & 15) << 2;
            float4 kv = *(const float4*)&kh[base + (size_t)(j0 + r) * DK + c4];
            Kt[(c4 + 0) * 68 + r] = kv.x;
            Kt[(c4 + 1) * 68 + r] = kv.y;
            Kt[(c4 + 2) * 68 + r] = kv.z;
            Kt[(c4 + 3) * 68 + r] = kv.w;
            float4 vv = *(const float4*)&vh[base + (size_t)(j0 + r) * DK + c4];
            *(float4*)&Vs[r * 68 + c4] = vv;
        }
        __syncthreads();

        // ---- QK^T: 8x4 microtile, packed pairs along rows ----
        ull acc[4][4];
#pragma unroll
        for (int p = 0; p < 4; p++)
#pragma unroll
            for (int j = 0; j < 4; j++) acc[p][j] = 0ULL;

#pragma unroll 2
        for (int kk = 0; kk < 64; kk++) {
            union { float4 f; ull u[2]; } qa, qb;
            qa.f = *(const float4*)&Qt[kk * 132 + row0];
            qb.f = *(const float4*)&Qt[kk * 132 + row0 + 4];
            float4 kf = *(const float4*)&Kt[kk * 68 + cg * 4];
            ull kb0 = pack2(kf.x, kf.x);
            ull kb1 = pack2(kf.y, kf.y);
            ull kb2 = pack2(kf.z, kf.z);
            ull kb3 = pack2(kf.w, kf.w);
            fma2(acc[0][0], qa.u[0], kb0); fma2(acc[0][1], qa.u[0], kb1);
            fma2(acc[0][2], qa.u[0], kb2); fma2(acc[0][3], qa.u[0], kb3);
            fma2(acc[1][0], qa.u[1], kb0); fma2(acc[1][1], qa.u[1], kb1);
            fma2(acc[1][2], qa.u[1], kb2); fma2(acc[1][3], qa.u[1], kb3);
            fma2(acc[2][0], qb.u[0], kb0); fma2(acc[2][1], qb.u[0], kb1);
            fma2(acc[2][2], qb.u[0], kb2); fma2(acc[2][3], qb.u[0], kb3);
            fma2(acc[3][0], qb.u[1], kb0); fma2(acc[3][1], qb.u[1], kb1);
            fma2(acc[3][2], qb.u[1], kb2); fma2(acc[3][3], qb.u[1], kb3);
        }

        float s[8][4];
#pragma unroll
        for (int p = 0; p < 4; p++)
#pragma unroll
            for (int j = 0; j < 4; j++)
                unpack2(acc[p][j], s[2 * p][j], s[2 * p + 1][j]);

        // ---- online softmax + p~ writes ----
#pragma unroll
        for (int ii = 0; ii < 8; ii++) {
            const int i = i0 + row0 + ii;
            float sc[4];
            float mx = -1e30f;
#pragma unroll
            for (int jj = 0; jj < 4; jj++) {
                float v = s[ii][jj] * 0.125f;
                if (j0 + cg * 4 + jj > i) v = -1e30f;
                sc[jj] = v;
                mx = fmaxf(mx, v);
            }
#pragma unroll
            for (int o = 1; o < 16; o <<= 1)
                mx = fmaxf(mx, __shfl_xor_sync(0xffffffffu, mx, o));
            float mnew = fmaxf(m[ii], mx);
            float esc = __expf(m[ii] - mnew);
            float p0 = __expf(sc[0] - mnew);
            float p1 = __expf(sc[1] - mnew);
            float p2 = __expf(sc[2] - mnew);
            float p3 = __expf(sc[3] - mnew);
            float ts = (p0 + p1) + (p2 + p3);
#pragma unroll
            for (int o = 1; o < 16; o <<= 1)
                ts += __shfl_xor_sync(0xffffffffu, ts, o);
            l[ii] = l[ii] * esc + ts;
            ull e2 = pack2(esc, esc);
            mul2(accpv[ii][0], accpv[ii][0], e2);
            mul2(accpv[ii][1], accpv[ii][1], e2);
            m[ii] = mnew;
            float4 pv4 = make_float4(p0, p1, p2, p3);
            *(float4*)&Ps[(row0 + ii) * 68 + cg * 4] = pv4;
            if (attn)
                *(float4*)&attn[((size_t)bh * S_LEN + i) * S_LEN + j0 + cg * 4] = pv4;
        }
        if (cg == 0) {
#pragma unroll
            for (int ii = 0; ii < 8; ii++)
                gsnap[((size_t)(bh * NTILE + jt)) * S_LEN + i0 + row0 + ii] = m[ii];
        }
        __syncthreads();

        // ---- PV: accpv += P~ @ V ----
#pragma unroll 2
        for (int kk = 0; kk < 64; kk++) {
            union { float4 f; ull u[2]; } vv;
            vv.f = *(const float4*)&Vs[kk * 68 + cg * 4];
            float pr[8];
#pragma unroll
            for (int ii = 0; ii < 8; ii++) pr[ii] = Ps[(row0 + ii) * 68 + kk];
#pragma unroll
            for (int ii = 0; ii < 8; ii++) {
                ull pp = pack2(pr[ii], pr[ii]);
                fma2(accpv[ii][0], pp, vv.u[0]);
                fma2(accpv[ii][1], pp, vv.u[1]);
            }
        }
    }

    // ---- epilogue: ctx = accpv / l ; store m, l ----
#pragma unroll
    for (int ii = 0; ii < 8; ii++) {
        const int i = i0 + row0 + ii;
        float linv = 1.f / l[ii];
        float o0, o1, o2, o3;
        unpack2(accpv[ii][0], o0, o1);
        unpack2(accpv[ii][1], o2, o3);
        *(float4*)&ctx[base + (size_t)i * DK + cg * 4] =
            make_float4(o0 * linv, o1 * linv, o2 * linv, o3 * linv);
    }
    if (cg == 0) {
#pragma unroll
        for (int ii = 0; ii < 8; ii++) {
            const int i = i0 + row0 + ii;
            gm[bh * S_LEN + i] = m[ii];
            gl[bh * S_LEN + i] = l[ii];
        }
    }
}

// ==========================================================================
// Fixup: attn = p~ * exp(m_snap - m_final) / l   (lower triangle),
//        attn = 0                                 (upper triangle).
// One block per (bh, row). In-place on the attn buffer.
// ==========================================================================
__global__ __launch_bounds__(256) void attn_fixup(
    const float* __restrict__ gm, const float* __restrict__ gl,
    const float* __restrict__ gsnap, float* __restrict__ attn)
{
    const int row = blockIdx.x;          // bh*2048 + i
    const int bh = row >> 11;
    const int i = row & 2047;
    const float mfin = gm[row];
    const float linv = 1.f / gl[row];
    const size_t rbase = (size_t)row * S_LEN;

#pragma unroll
    for (int t = 0; t < 2; t++) {
        int j4 = (threadIdx.x + t * 256) * 4;
        float4 o;
        if (j4 + 3 <= i) {
            int jt = j4 >> 6;
            float f = __expf(gsnap[(size_t)(bh * NTILE + jt) * S_LEN + i] - mfin) * linv;
            float4 p = *(const float4*)&attn[rbase + j4];
            o = make_float4(p.x * f, p.y * f, p.z * f, p.w * f);
        } else if (j4 <= i) {
            int jt = j4 >> 6;
            float f = __expf(gsnap[(size_t)(bh * NTILE + jt) * S_LEN + i] - mfin) * linv;
            float4 p = *(const float4*)&attn[rbase + j4];
            o.x = (j4 + 0 <= i) ? p.x * f : 0.f;
            o.y = (j4 + 1 <= i) ? p.y * f : 0.f;
            o.z = (j4 + 2 <= i) ? p.z * f : 0.f;
            o.w = (j4 + 3 <= i) ? p.w * f : 0.f;
        } else {
            o = make_float4(0.f, 0.f, 0.f, 0.f);
        }
        *(float4*)&attn[rbase + j4] = o;
    }
}

// ==========================================================================
// host launch
// ==========================================================================
extern "C" void kernel_launch(void* const* d_in, const int* in_sizes, int n_in,
                              void* d_out, int out_size)
{
    const float* q  = (const float*)d_in[0];
    const float* k  = (const float*)d_in[1];
    const float* v  = (const float*)d_in[2];
    // d_in[3] = mask (causal tril; structure exploited directly)
    const float* wq = (const float*)d_in[4];
    const float* bq = (const float*)d_in[5];
    const float* wk = (const float*)d_in[6];
    const float* bk = (const float*)d_in[7];
    const float* wv = (const float*)d_in[8];
    const float* bv = (const float*)d_in[9];
    const float* wo = (const float*)d_in[10];
    const float* bo = (const float*)d_in[11];

    float *qh, *kh, *vh, *ctx, *gm, *gl, *gsnap;
    cudaGetSymbolAddress((void**)&qh, g_qh);
    cudaGetSymbolAddress((void**)&kh, g_kh);
    cudaGetSymbolAddress((void**)&vh, g_vh);
    cudaGetSymbolAddress((void**)&ctx, g_ctx);
    cudaGetSymbolAddress((void**)&gm, g_m);
    cudaGetSymbolAddress((void**)&gl, g_l);
    cudaGetSymbolAddress((void**)&gsnap, g_snap);

    float* outbuf = (float*)d_out;
    float* out_ptr = nullptr;
    float* attn_ptr = nullptr;
    const long long OUT_N  = (long long)BATCH * S_LEN * DMODEL;        // 4,194,304
    const long long ATTN_N = (long long)BH * S_LEN * S_LEN;            // 134,217,728
    long long osz = (long long)out_size;
    if (osz >= OUT_N + ATTN_N)      { out_ptr = outbuf; attn_ptr = outbuf + OUT_N; }
    else if (osz == OUT_N)          { out_ptr = outbuf; }
    else                            { attn_ptr = outbuf; }

    const int ATTN_SMEM = (64 * 132 + 64 * 68 + 64 * 68 + 128 * 68) * 4;  // 103424
    cudaFuncSetAttribute(attn_fused, cudaFuncAttributeMaxDynamicSharedMemorySize, ATTN_SMEM);

    dim3 ggrid(DMODEL / 128, MROWS / 128);  // (8, 32)
    gemm128<false, true><<<ggrid, 256>>>(q, wq, bq, qh);
    gemm128<false, true><<<ggrid, 256>>>(k, wk, bk, kh);
    gemm128<false, true><<<ggrid, 256>>>(v, wv, bv, vh);

    dim3 agrid(BH, S_LEN / 128);            // (32, 16)
    attn_fused<<<agrid, 256, ATTN_SMEM>>>(qh, kh, vh, attn_ptr, ctx, gm, gl, gsnap);

    if (attn_ptr) {
        attn_fixup<<<BH * S_LEN, 256>>>(gm, gl, gsnap, attn_ptr);
    }

    if (out_ptr) {
        gemm128<true, false><<<ggrid, 256>>>(ctx, wo, bo, out_ptr);
    }
}

// round 5
// speedup vs baseline: 1.7098x; 1.3215x over previous
#include <cuda_runtime.h>
#include <cuda_bf16.h>
#include <cstdint>

typedef unsigned long long ull;

#define S_LEN 2048
#define DMODEL 1024
#define NHEADS 16
#define DK 64
#define BATCH 2
#define BH (BATCH * NHEADS)
#define MROWS (BATCH * S_LEN)   // 4096
#define NTILE 32                // 2048/64 key tiles per row
#define GK 2048                 // storage: [hi(1024) | lo(1024)]

// ---------------- scratch (device globals; no allocation allowed) ----------
__device__ float g_qh[BH * S_LEN * DK];
__device__ float g_kh[BH * S_LEN * DK];
__device__ float g_vh[BH * S_LEN * DK];
__device__ float g_ctx[BH * S_LEN * DK];
__device__ float g_m[BH * S_LEN];
__device__ float g_l[BH * S_LEN];
__device__ float g_snap[BH * NTILE * S_LEN];
__device__ __nv_bfloat16 g_wb[4 * DMODEL * GK];   // weights, [n][k] hi|lo
__device__ __nv_bfloat16 g_xb[MROWS * GK];        // activations, [m][k] hi|lo

// ---------------- packed f32x2 helpers (FFMA2) ------------------------------
__device__ __forceinline__ ull pack2(float x, float y) {
    ull r; asm("mov.b64 %0, {%1, %2};" : "=l"(r) : "f"(x), "f"(y)); return r;
}
__device__ __forceinline__ void unpack2(ull v, float& x, float& y) {
    asm("mov.b64 {%0, %1}, %2;" : "=f"(x), "=f"(y) : "l"(v));
}
__device__ __forceinline__ void fma2(ull& d, ull a, ull b) {
    asm("fma.rn.f32x2 %0, %1, %2, %0;" : "+l"(d) : "l"(a), "l"(b));
}
__device__ __forceinline__ void mul2(ull& d, ull a, ull b) {
    asm("mul.rn.f32x2 %0, %1, %2;" : "=l"(d) : "l"(a), "l"(b));
}

// ---------------- HMMA primitives ------------------------------------------
__device__ __forceinline__ uint32_t smem_u32(const void* p) {
    uint32_t a;
    asm("{ .reg .u64 t; cvta.to.shared.u64 t, %1; cvt.u32.u64 %0, t; }" : "=r"(a) : "l"(p));
    return a;
}
__device__ __forceinline__ void ldmx4(uint32_t* r, uint32_t addr) {
    asm volatile("ldmatrix.sync.aligned.m8n8.x4.shared.b16 {%0,%1,%2,%3}, [%4];"
                 : "=r"(r[0]), "=r"(r[1]), "=r"(r[2]), "=r"(r[3]) : "r"(addr));
}
__device__ __forceinline__ void mma16816(float* c, const uint32_t* a, const uint32_t* b) {
    asm volatile(
        "mma.sync.aligned.m16n8k16.row.col.f32.bf16.bf16.f32 "
        "{%0,%1,%2,%3}, {%4,%5,%6,%7}, {%8,%9}, {%0,%1,%2,%3};"
        : "+f"(c[0]), "+f"(c[1]), "+f"(c[2]), "+f"(c[3])
        : "r"(a[0]), "r"(a[1]), "r"(a[2]), "r"(a[3]), "r"(b[0]), "r"(b[1]));
}

// ==========================================================================
// Conversion kernels (fp32 -> hi|lo bf16 split along K)
// ==========================================================================
__global__ __launch_bounds__(256) void conv_w(
    const float* __restrict__ W, __nv_bfloat16* __restrict__ Wb)
{
    __shared__ float t[32][33];
    const int bx = blockIdx.x * 32;   // n
    const int by = blockIdx.y * 32;   // k
    const int tx = threadIdx.x & 31;
    const int ty = threadIdx.x >> 5;  // 0..7
#pragma unroll
    for (int i = 0; i < 32; i += 8)
        t[ty + i][tx] = W[(size_t)(by + ty + i) * DMODEL + bx + tx];
    __syncthreads();
#pragma unroll
    for (int i = 0; i < 32; i += 8) {
        int n = bx + ty + i, k = by + tx;
        float w = t[tx][ty + i];
        __nv_bfloat16 hi = __float2bfloat16(w);
        __nv_bfloat16 lo = __float2bfloat16(w - __bfloat162float(hi));
        Wb[(size_t)n * GK + k] = hi;
        Wb[(size_t)n * GK + DMODEL + k] = lo;
    }
}

template <bool SPLIT_IN>
__global__ __launch_bounds__(256) void conv_a(
    const float* __restrict__ X, __nv_bfloat16* __restrict__ Xb)
{
    int idx = blockIdx.x * 256 + threadIdx.x;
    int m = idx >> 10, k = idx & 1023;
    float x;
    if (!SPLIT_IN) {
        x = X[idx];
    } else {
        int b = m >> 11, s = m & 2047, h = k >> 6, d = k & 63;
        x = X[(((size_t)(b * 16 + h)) * S_LEN + s) * DK + d];
    }
    __nv_bfloat16 hi = __float2bfloat16(x);
    __nv_bfloat16 lo = __float2bfloat16(x - __bfloat162float(hi));
    Xb[(size_t)m * GK + k] = hi;
    Xb[(size_t)m * GK + DMODEL + k] = lo;
}

// ==========================================================================
// HMMA bf16 GEMM with 3-term split:
//   C = A_hi*B_hi + A_hi*B_lo + A_lo*B_hi   (A_lo*B_lo dropped, ~2^-18)
// Logical K = 3072 = 3 segments x 1024; seg -> (A k-offset, B k-offset):
//   seg0: (0, 0)  seg1: (0, 1024)  seg2: (1024, 0)
// CTA 128x128, K-chunk 32, 256 threads (8 warps, 4m x 2n), warp tile 32x64.
// ==========================================================================
#define KC 32
#define NCH 96                   // 3 * 1024 / KC
#define LDS_STRIDE 40

__device__ __forceinline__ void seg_off(int c, int& ka, int& kb) {
    int seg = c >> 5;            // 0..2  (32 chunks per segment)
    int base = (c & 31) * KC;
    ka = base + ((seg == 2) ? DMODEL : 0);
    kb = base + ((seg == 1) ? DMODEL : 0);
}

template <bool SPLIT_OUT>
__global__ __launch_bounds__(256) void gemm_hmma(
    const __nv_bfloat16* __restrict__ Ab, const __nv_bfloat16* __restrict__ Bb,
    const float* __restrict__ bias, float* __restrict__ C)
{
    __shared__ __nv_bfloat16 As[2][128 * LDS_STRIDE];
    __shared__ __nv_bfloat16 Bs[2][128 * LDS_STRIDE];

    const int tid = threadIdx.x;
    const int wid = tid >> 5, lane = tid & 31;
    const int m0 = blockIdx.y * 128, n0 = blockIdx.x * 128;
    const int warp_m = (wid & 3) * 32;   // 4 warps along m
    const int warp_n = (wid >> 2) * 64;  // 2 warps along n

    const __nv_bfloat16* Arow = Ab + (size_t)m0 * GK;
    const __nv_bfloat16* Brow = Bb + (size_t)n0 * GK;

    const int r0 = tid >> 2, c0 = (tid & 3) * 8;
    const int r1 = (tid + 256) >> 2;

    float acc[2][8][4];
#pragma unroll
    for (int mi = 0; mi < 2; mi++)
#pragma unroll
        for (int ni = 0; ni < 8; ni++)
#pragma unroll
            for (int j = 0; j < 4; j++) acc[mi][ni][j] = 0.f;

    // preload chunk 0 (seg0: ka=kb=0)
    {
        uint4 a0 = *(const uint4*)(Arow + (size_t)r0 * GK + c0);
        uint4 a1 = *(const uint4*)(Arow + (size_t)r1 * GK + c0);
        uint4 b0 = *(const uint4*)(Brow + (size_t)r0 * GK + c0);
        uint4 b1 = *(const uint4*)(Brow + (size_t)r1 * GK + c0);
        *(uint4*)(As[0] + r0 * LDS_STRIDE + c0) = a0;
        *(uint4*)(As[0] + r1 * LDS_STRIDE + c0) = a1;
        *(uint4*)(Bs[0] + r0 * LDS_STRIDE + c0) = b0;
        *(uint4*)(Bs[0] + r1 * LDS_STRIDE + c0) = b1;
    }
    __syncthreads();

    for (int c = 0; c < NCH; c++) {
        const int cur = c & 1, nxt = cur ^ 1;
        uint4 pa0, pa1, pb0, pb1;
        if (c + 1 < NCH) {
            int ka, kb;
            seg_off(c + 1, ka, kb);
            pa0 = *(const uint4*)(Arow + (size_t)r0 * GK + ka + c0);
            pa1 = *(const uint4*)(Arow + (size_t)r1 * GK + ka + c0);
            pb0 = *(const uint4*)(Brow + (size_t)r0 * GK + kb + c0);
            pb1 = *(const uint4*)(Brow + (size_t)r1 * GK + kb + c0);
        }

        const uint32_t sa = smem_u32(As[cur]);
        const uint32_t sbm = smem_u32(Bs[cur]);
#pragma unroll
        for (int kk2 = 0; kk2 < 2; kk2++) {
            const int kk = kk2 * 16;
            uint32_t af[2][4];
#pragma unroll
            for (int mi = 0; mi < 2; mi++) {
                uint32_t addr = sa + ((warp_m + mi * 16 + (lane & 15)) * LDS_STRIDE
                                      + kk + (lane >> 4) * 8) * 2;
                ldmx4(af[mi], addr);
            }
            uint32_t bf[8][2];
#pragma unroll
            for (int ni2 = 0; ni2 < 4; ni2++) {
                uint32_t r[4];
                uint32_t addr = sbm + ((warp_n + ni2 * 16 + (lane & 7) + 8 * ((lane >> 3) & 1))
                                       * LDS_STRIDE + kk + (lane >> 4) * 8) * 2;
                ldmx4(r, addr);
                bf[2 * ni2][0] = r[0]; bf[2 * ni2 + 1][0] = r[1];
                bf[2 * ni2][1] = r[2]; bf[2 * ni2 + 1][1] = r[3];
            }
#pragma unroll
            for (int mi = 0; mi < 2; mi++)
#pragma unroll
                for (int ni = 0; ni < 8; ni++)
                    mma16816(acc[mi][ni], af[mi], bf[ni]);
        }

        if (c + 1 < NCH) {
            *(uint4*)(As[nxt] + r0 * LDS_STRIDE + c0) = pa0;
            *(uint4*)(As[nxt] + r1 * LDS_STRIDE + c0) = pa1;
            *(uint4*)(Bs[nxt] + r0 * LDS_STRIDE + c0) = pb0;
            *(uint4*)(Bs[nxt] + r1 * LDS_STRIDE + c0) = pb1;
        }
        __syncthreads();
    }

    // ---- epilogue: bias + store ----
#pragma unroll
    for (int ni = 0; ni < 8; ni++) {
        const int n = n0 + warp_n + ni * 8 + (lane & 3) * 2;
        const float bv0 = __ldg(&bias[n]);
        const float bv1 = __ldg(&bias[n + 1]);
#pragma unroll
        for (int mi = 0; mi < 2; mi++) {
#pragma unroll
            for (int half = 0; half < 2; half++) {
                const int m = m0 + warp_m + mi * 16 + (lane >> 2) + half * 8;
                float2 o = make_float2(acc[mi][ni][2 * half] + bv0,
                                       acc[mi][ni][2 * half + 1] + bv1);
                if (!SPLIT_OUT) {
                    *(float2*)&C[(size_t)m * DMODEL + n] = o;
                } else {
                    int b = m >> 11, s = m & 2047;
                    int h = n >> 6, d = n & 63;
                    *(float2*)&C[(((size_t)(b * 16 + h)) * S_LEN + s) * DK + d] = o;
                }
            }
        }
    }
}

// ==========================================================================
// Fused single-pass causal attention (FFMA2 scalar, from R2).
// ==========================================================================
__global__ __launch_bounds__(256) void attn_fused(
    const float* __restrict__ qh, const float* __restrict__ kh,
    const float* __restrict__ vh,
    float* __restrict__ attn, float* __restrict__ ctx,
    float* __restrict__ gm, float* __restrict__ gl,
    float* __restrict__ gsnap)
{
    extern __shared__ float smf[];
    float* Qt = smf;               // [64][132]
    float* Kt = Qt + 64 * 132;     // [64][68]
    float* Vs = Kt + 64 * 68;      // [64][68]
    float* Ps = Vs + 64 * 68;      // [128][68]

    const int tid = threadIdx.x;
    const int bh = blockIdx.x;
    const int qt = blockIdx.y;
    const size_t base = (size_t)bh * (S_LEN * DK);
    const int i0 = qt * 128;
    const int rg = tid >> 4, cg = tid & 15;
    const int row0 = rg * 8;

#pragma unroll
    for (int li = 0; li < 8; li++) {
        int lin = tid + li * 256;
        int r = lin >> 4, c4 = (lin & 15) << 2;
        float4 v = *(const float4*)&qh[base + (size_t)(i0 + r) * DK + c4];
        Qt[(c4 + 0) * 132 + r] = v.x;
        Qt[(c4 + 1) * 132 + r] = v.y;
        Qt[(c4 + 2) * 132 + r] = v.z;
        Qt[(c4 + 3) * 132 + r] = v.w;
    }

    float m[8], l[8];
    ull accpv[8][2];
#pragma unroll
    for (int ii = 0; ii < 8; ii++) {
        m[ii] = -1e30f; l[ii] = 0.f;
        accpv[ii][0] = 0ULL; accpv[ii][1] = 0ULL;
    }

    const int ntiles = 2 * qt + 2;
    for (int jt = 0; jt < ntiles; jt++) {
        const int j0 = jt * 64;
        __syncthreads();
#pragma unroll
        for (int li = 0; li < 4; li++) {
            int lin = tid + li * 256;
            int r = lin >> 4, c4 = (lin & 15) << 2;
            float4 kv = *(const float4*)&kh[base + (size_t)(j0 + r) * DK + c4];
            Kt[(c4 + 0) * 68 + r] = kv.x;
            Kt[(c4 + 1) * 68 + r] = kv.y;
            Kt[(c4 + 2) * 68 + r] = kv.z;
            Kt[(c4 + 3) * 68 + r] = kv.w;
            float4 vv = *(const float4*)&vh[base + (size_t)(j0 + r) * DK + c4];
            *(float4*)&Vs[r * 68 + c4] = vv;
        }
        __syncthreads();

        ull acc[4][4];
#pragma unroll
        for (int p = 0; p < 4; p++)
#pragma unroll
            for (int j = 0; j < 4; j++) acc[p][j] = 0ULL;

#pragma unroll 2
        for (int kk = 0; kk < 64; kk++) {
            union { float4 f; ull u[2]; } qa, qb;
            qa.f = *(const float4*)&Qt[kk * 132 + row0];
            qb.f = *(const float4*)&Qt[kk * 132 + row0 + 4];
            float4 kf = *(const float4*)&Kt[kk * 68 + cg * 4];
            ull kb0 = pack2(kf.x, kf.x);
            ull kb1 = pack2(kf.y, kf.y);
            ull kb2 = pack2(kf.z, kf.z);
            ull kb3 = pack2(kf.w, kf.w);
            fma2(acc[0][0], qa.u[0], kb0); fma2(acc[0][1], qa.u[0], kb1);
            fma2(acc[0][2], qa.u[0], kb2); fma2(acc[0][3], qa.u[0], kb3);
            fma2(acc[1][0], qa.u[1], kb0); fma2(acc[1][1], qa.u[1], kb1);
            fma2(acc[1][2], qa.u[1], kb2); fma2(acc[1][3], qa.u[1], kb3);
            fma2(acc[2][0], qb.u[0], kb0); fma2(acc[2][1], qb.u[0], kb1);
            fma2(acc[2][2], qb.u[0], kb2); fma2(acc[2][3], qb.u[0], kb3);
            fma2(acc[3][0], qb.u[1], kb0); fma2(acc[3][1], qb.u[1], kb1);
            fma2(acc[3][2], qb.u[1], kb2); fma2(acc[3][3], qb.u[1], kb3);
        }

        float s[8][4];
#pragma unroll
        for (int p = 0; p < 4; p++)
#pragma unroll
            for (int j = 0; j < 4; j++)
                unpack2(acc[p][j], s[2 * p][j], s[2 * p + 1][j]);

#pragma unroll
        for (int ii = 0; ii < 8; ii++) {
            const int i = i0 + row0 + ii;
            float sc[4];
            float mx = -1e30f;
#pragma unroll
            for (int jj = 0; jj < 4; jj++) {
                float v = s[ii][jj] * 0.125f;
                if (j0 + cg * 4 + jj > i) v = -1e30f;
                sc[jj] = v;
                mx = fmaxf(mx, v);
            }
#pragma unroll
            for (int o = 1; o < 16; o <<= 1)
                mx = fmaxf(mx, __shfl_xor_sync(0xffffffffu, mx, o));
            float mnew = fmaxf(m[ii], mx);
            float esc = __expf(m[ii] - mnew);
            float p0 = __expf(sc[0] - mnew);
            float p1 = __expf(sc[1] - mnew);
            float p2 = __expf(sc[2] - mnew);
            float p3 = __expf(sc[3] - mnew);
            float ts = (p0 + p1) + (p2 + p3);
#pragma unroll
            for (int o = 1; o < 16; o <<= 1)
                ts += __shfl_xor_sync(0xffffffffu, ts, o);
            l[ii] = l[ii] * esc + ts;
            ull e2 = pack2(esc, esc);
            mul2(accpv[ii][0], accpv[ii][0], e2);
            mul2(accpv[ii][1], accpv[ii][1], e2);
            m[ii] = mnew;
            float4 pv4 = make_float4(p0, p1, p2, p3);
            *(float4*)&Ps[(row0 + ii) * 68 + cg * 4] = pv4;
            if (attn)
                *(float4*)&attn[((size_t)bh * S_LEN + i) * S_LEN + j0 + cg * 4] = pv4;
        }
        if (cg == 0) {
#pragma unroll
            for (int ii = 0; ii < 8; ii++)
                gsnap[((size_t)(bh * NTILE + jt)) * S_LEN + i0 + row0 + ii] = m[ii];
        }
        __syncthreads();

#pragma unroll 2
        for (int kk = 0; kk < 64; kk++) {
            union { float4 f; ull u[2]; } vv;
            vv.f = *(const float4*)&Vs[kk * 68 + cg * 4];
            float pr[8];
#pragma unroll
            for (int ii = 0; ii < 8; ii++) pr[ii] = Ps[(row0 + ii) * 68 + kk];
#pragma unroll
            for (int ii = 0; ii < 8; ii++) {
                ull pp = pack2(pr[ii], pr[ii]);
                fma2(accpv[ii][0], pp, vv.u[0]);
                fma2(accpv[ii][1], pp, vv.u[1]);
            }
        }
    }

#pragma unroll
    for (int ii = 0; ii < 8; ii++) {
        const int i = i0 + row0 + ii;
        float linv = 1.f / l[ii];
        float o0, o1, o2, o3;
        unpack2(accpv[ii][0], o0, o1);
        unpack2(accpv[ii][1], o2, o3);
        *(float4*)&ctx[base + (size_t)i * DK + cg * 4] =
            make_float4(o0 * linv, o1 * linv, o2 * linv, o3 * linv);
    }
    if (cg == 0) {
#pragma unroll
        for (int ii = 0; ii < 8; ii++) {
            const int i = i0 + row0 + ii;
            gm[bh * S_LEN + i] = m[ii];
            gl[bh * S_LEN + i] = l[ii];
        }
    }
}

// ==========================================================================
// Fixup: normalize attn probabilities + zero upper triangle. In-place.
// ==========================================================================
__global__ __launch_bounds__(256) void attn_fixup(
    const float* __restrict__ gm, const float* __restrict__ gl,
    const float* __restrict__ gsnap, float* __restrict__ attn)
{
    const int row = blockIdx.x;
    const int bh = row >> 11;
    const int i = row & 2047;
    const float mfin = gm[row];
    const float linv = 1.f / gl[row];
    const size_t rbase = (size_t)row * S_LEN;

#pragma unroll
    for (int t = 0; t < 2; t++) {
        int j4 = (threadIdx.x + t * 256) * 4;
        float4 o;
        if (j4 + 3 <= i) {
            int jt = j4 >> 6;
            float f = __expf(gsnap[(size_t)(bh * NTILE + jt) * S_LEN + i] - mfin) * linv;
            float4 p = *(const float4*)&attn[rbase + j4];
            o = make_float4(p.x * f, p.y * f, p.z * f, p.w * f);
        } else if (j4 <= i) {
            int jt = j4 >> 6;
            float f = __expf(gsnap[(size_t)(bh * NTILE + jt) * S_LEN + i] - mfin) * linv;
            float4 p = *(const float4*)&attn[rbase + j4];
            o.x = (j4 + 0 <= i) ? p.x * f : 0.f;
            o.y = (j4 + 1 <= i) ? p.y * f : 0.f;
            o.z = (j4 + 2 <= i) ? p.z * f : 0.f;
            o.w = (j4 + 3 <= i) ? p.w * f : 0.f;
        } else {
            o = make_float4(0.f, 0.f, 0.f, 0.f);
        }
        *(float4*)&attn[rbase + j4] = o;
    }
}

// ==========================================================================
// host launch
// ==========================================================================
extern "C" void kernel_launch(void* const* d_in, const int* in_sizes, int n_in,
                              void* d_out, int out_size)
{
    const float* q  = (const float*)d_in[0];
    const float* k  = (const float*)d_in[1];
    const float* v  = (const float*)d_in[2];
    const float* wq = (const float*)d_in[4];
    const float* bq = (const float*)d_in[5];
    const float* wk = (const float*)d_in[6];
    const float* bk = (const float*)d_in[7];
    const float* wv = (const float*)d_in[8];
    const float* bv = (const float*)d_in[9];
    const float* wo = (const float*)d_in[10];
    const float* bo = (const float*)d_in[11];

    float *qh, *kh, *vh, *ctx, *gm, *gl, *gsnap;
    __nv_bfloat16 *wb, *xb;
    cudaGetSymbolAddress((void**)&qh, g_qh);
    cudaGetSymbolAddress((void**)&kh, g_kh);
    cudaGetSymbolAddress((void**)&vh, g_vh);
    cudaGetSymbolAddress((void**)&ctx, g_ctx);
    cudaGetSymbolAddress((void**)&gm, g_m);
    cudaGetSymbolAddress((void**)&gl, g_l);
    cudaGetSymbolAddress((void**)&gsnap, g_snap);
    cudaGetSymbolAddress((void**)&wb, g_wb);
    cudaGetSymbolAddress((void**)&xb, g_xb);

    float* outbuf = (float*)d_out;
    float* out_ptr = nullptr;
    float* attn_ptr = nullptr;
    const long long OUT_N  = (long long)BATCH * S_LEN * DMODEL;
    const long long ATTN_N = (long long)BH * S_LEN * S_LEN;
    long long osz = (long long)out_size;
    if (osz >= OUT_N + ATTN_N)      { out_ptr = outbuf; attn_ptr = outbuf + OUT_N; }
    else if (osz == OUT_N)          { out_ptr = outbuf; }
    else                            { attn_ptr = outbuf; }

    const int ATTN_SMEM = (64 * 132 + 64 * 68 + 64 * 68 + 128 * 68) * 4;  // 103424
    cudaFuncSetAttribute(attn_fused, cudaFuncAttributeMaxDynamicSharedMemorySize, ATTN_SMEM);

    dim3 tgrid(32, 32);                      // conv_w transpose tiles
    conv_w<<<tgrid, 256>>>(wq, wb + 0 * (size_t)DMODEL * GK);
    conv_w<<<tgrid, 256>>>(wk, wb + 1 * (size_t)DMODEL * GK);
    conv_w<<<tgrid, 256>>>(wv, wb + 2 * (size_t)DMODEL * GK);
    conv_w<<<tgrid, 256>>>(wo, wb + 3 * (size_t)DMODEL * GK);

    dim3 ggrid(DMODEL / 128, MROWS / 128);   // (8, 32)
    const int AGRID = MROWS * DMODEL / 256;  // 16384

    conv_a<false><<<AGRID, 256>>>(q, xb);
    gemm_hmma<true><<<ggrid, 256>>>(xb, wb + 0 * (size_t)DMODEL * GK, bq, qh);
    conv_a<false><<<AGRID, 256>>>(k, xb);
    gemm_hmma<true><<<ggrid, 256>>>(xb, wb + 1 * (size_t)DMODEL * GK, bk, kh);
    conv_a<false><<<AGRID, 256>>>(v, xb);
    gemm_hmma<true><<<ggrid, 256>>>(xb, wb + 2 * (size_t)DMODEL * GK, bv, vh);

    dim3 agrid(BH, S_LEN / 128);             // (32, 16)
    attn_fused<<<agrid, 256, ATTN_SMEM>>>(qh, kh, vh, attn_ptr, ctx, gm, gl, gsnap);

    if (attn_ptr) {
        attn_fixup<<<BH * S_LEN, 256>>>(gm, gl, gsnap, attn_ptr);
    }

    if (out_ptr) {
        conv_a<true><<<AGRID, 256>>>(ctx, xb);
        gemm_hmma<false><<<ggrid, 256>>>(xb, wb + 3 * (size_t)DMODEL * GK, bo, out_ptr);
    }
}

// round 6
// speedup vs baseline: 4.3876x; 2.5661x over previous
#include <cuda_runtime.h>
#include <cuda_fp16.h>
#include <cstdint>

#define S_LEN 2048
#define DMODEL 1024
#define NHEADS 16
#define DK 64
#define BATCH 2
#define BH (BATCH * NHEADS)
#define MROWS (BATCH * S_LEN)   // 4096
#define NTILE 32                // 2048/64 key tiles per row

// ---------------- scratch (device globals; no allocation allowed) ----------
__device__ float g_ctx[BH * S_LEN * DK];
__device__ float g_m[BH * S_LEN];
__device__ float g_l[BH * S_LEN];
__device__ float g_snap[BH * NTILE * S_LEN];      // log2-domain running max
__device__ __half g_wh[4 * DMODEL * DMODEL];      // weights [n][k] f16
__device__ __half g_xh[MROWS * DMODEL];           // activations [m][k] f16
__device__ __half g_qhf[BH * S_LEN * DK];         // [bh][s][dk]
__device__ __half g_khf[BH * S_LEN * DK];         // [bh][s][dk]
__device__ __half g_vtf[BH * DK * S_LEN];         // [bh][dk][s]  (transposed)

// ---------------- primitives ------------------------------------------------
__device__ __forceinline__ uint32_t smem_u32(const void* p) {
    uint32_t a;
    asm("{ .reg .u64 t; cvta.to.shared.u64 t, %1; cvt.u32.u64 %0, t; }" : "=r"(a) : "l"(p));
    return a;
}
__device__ __forceinline__ void ldmx4(uint32_t* r, uint32_t addr) {
    asm volatile("ldmatrix.sync.aligned.m8n8.x4.shared.b16 {%0,%1,%2,%3}, [%4];"
                 : "=r"(r[0]), "=r"(r[1]), "=r"(r[2]), "=r"(r[3]) : "r"(addr));
}
__device__ __forceinline__ void mma16816h(float* c, const uint32_t* a, const uint32_t* b) {
    asm volatile(
        "mma.sync.aligned.m16n8k16.row.col.f32.f16.f16.f32 "
        "{%0,%1,%2,%3}, {%4,%5,%6,%7}, {%8,%9}, {%0,%1,%2,%3};"
        : "+f"(c[0]), "+f"(c[1]), "+f"(c[2]), "+f"(c[3])
        : "r"(a[0]), "r"(a[1]), "r"(a[2]), "r"(a[3]), "r"(b[0]), "r"(b[1]));
}
// pack two f32 into f16x2: lo half = first arg, hi half = second arg
__device__ __forceinline__ uint32_t pack_f16x2(float lo, float hi) {
    uint32_t d;
    asm("cvt.rn.f16x2.f32 %0, %1, %2;" : "=r"(d) : "f"(hi), "f"(lo));
    return d;
}
__device__ __forceinline__ uint32_t ex2_f16x2(uint32_t x) {
    uint32_t r;
    asm("ex2.approx.f16x2 %0, %1;" : "=r"(r) : "r"(x));
    return r;
}

// ==========================================================================
// Conversion kernels (fp32 -> f16)
// ==========================================================================
__global__ __launch_bounds__(256) void conv_w(
    const float* __restrict__ W, __half* __restrict__ Wh)
{
    __shared__ float t[32][33];
    const int bx = blockIdx.x * 32;   // n
    const int by = blockIdx.y * 32;   // k
    const int tx = threadIdx.x & 31;
    const int ty = threadIdx.x >> 5;  // 0..7
#pragma unroll
    for (int i = 0; i < 32; i += 8)
        t[ty + i][tx] = W[(size_t)(by + ty + i) * DMODEL + bx + tx];
    __syncthreads();
#pragma unroll
    for (int i = 0; i < 32; i += 8) {
        int n = bx + ty + i, k = by + tx;
        Wh[(size_t)n * DMODEL + k] = __float2half(t[tx][ty + i]);
    }
}

template <bool SPLIT_IN>
__global__ __launch_bounds__(256) void conv_a(
    const float* __restrict__ X, __half* __restrict__ Xh)
{
    int idx = blockIdx.x * 256 + threadIdx.x;
    int m = idx >> 10, k = idx & 1023;
    float x;
    if (!SPLIT_IN) {
        x = X[idx];
    } else {
        int b = m >> 11, s = m & 2047, h = k >> 6, d = k & 63;
        x = X[(((size_t)(b * 16 + h)) * S_LEN + s) * DK + d];
    }
    Xh[idx] = __float2half(x);
}

// ==========================================================================
// HMMA fp16 GEMM: [4096,1024] @ [1024,1024]^T + bias
// CTA 128x128, K-chunk 32, 256 threads (8 warps, 4m x 2n), warp tile 32x64.
// MODE 0: fp32 C [m][1024]
// MODE 1: f16 head-split [bh][s][64]          (q, k)
// MODE 2: f16 head-split transposed [bh][64][s] (v)
// ==========================================================================
#define KC 32
#define NCH (DMODEL / KC)    // 32
#define LDS_STRIDE 40

template <int MODE>
__global__ __launch_bounds__(256) void gemm_hmma(
    const __half* __restrict__ Ah, const __half* __restrict__ Bhm,
    const float* __restrict__ bias, float* __restrict__ C, __half* __restrict__ Ch)
{
    __shared__ __half As[2][128 * LDS_STRIDE];
    __shared__ __half Bs[2][128 * LDS_STRIDE];

    const int tid = threadIdx.x;
    const int wid = tid >> 5, lane = tid & 31;
    const int m0 = blockIdx.y * 128, n0 = blockIdx.x * 128;
    const int warp_m = (wid & 3) * 32;
    const int warp_n = (wid >> 2) * 64;

    const __half* Arow = Ah + (size_t)m0 * DMODEL;
    const __half* Brow = Bhm + (size_t)n0 * DMODEL;

    // per tile: 128 rows x 32 k = 512 uint4 per operand, 2 per thread
    const int r0 = tid >> 2, c0 = (tid & 3) * 8;
    const int r1 = (tid + 256) >> 2;

    float acc[2][8][4];
#pragma unroll
    for (int mi = 0; mi < 2; mi++)
#pragma unroll
        for (int ni = 0; ni < 8; ni++)
#pragma unroll
            for (int j = 0; j < 4; j++) acc[mi][ni][j] = 0.f;

    {
        uint4 a0 = *(const uint4*)(Arow + (size_t)r0 * DMODEL + c0);
        uint4 a1 = *(const uint4*)(Arow + (size_t)r1 * DMODEL + c0);
        uint4 b0 = *(const uint4*)(Brow + (size_t)r0 * DMODEL + c0);
        uint4 b1 = *(const uint4*)(Brow + (size_t)r1 * DMODEL + c0);
        *(uint4*)(As[0] + r0 * LDS_STRIDE + c0) = a0;
        *(uint4*)(As[0] + r1 * LDS_STRIDE + c0) = a1;
        *(uint4*)(Bs[0] + r0 * LDS_STRIDE + c0) = b0;
        *(uint4*)(Bs[0] + r1 * LDS_STRIDE + c0) = b1;
    }
    __syncthreads();

    for (int c = 0; c < NCH; c++) {
        const int cur = c & 1, nxt = cur ^ 1;
        uint4 pa0, pa1, pb0, pb1;
        if (c + 1 < NCH) {
            const int ko = (c + 1) * KC;
            pa0 = *(const uint4*)(Arow + (size_t)r0 * DMODEL + ko + c0);
            pa1 = *(const uint4*)(Arow + (size_t)r1 * DMODEL + ko + c0);
            pb0 = *(const uint4*)(Brow + (size_t)r0 * DMODEL + ko + c0);
            pb1 = *(const uint4*)(Brow + (size_t)r1 * DMODEL + ko + c0);
        }

        const uint32_t sa = smem_u32(As[cur]);
        const uint32_t sbm = smem_u32(Bs[cur]);
#pragma unroll
        for (int kk2 = 0; kk2 < 2; kk2++) {
            const int kk = kk2 * 16;
            uint32_t af[2][4];
#pragma unroll
            for (int mi = 0; mi < 2; mi++) {
                uint32_t addr = sa + ((warp_m + mi * 16 + (lane & 15)) * LDS_STRIDE
                                      + kk + (lane >> 4) * 8) * 2;
                ldmx4(af[mi], addr);
            }
            uint32_t bf[8][2];
#pragma unroll
            for (int ni2 = 0; ni2 < 4; ni2++) {
                uint32_t r[4];
                uint32_t addr = sbm + ((warp_n + ni2 * 16 + (lane & 7) + 8 * ((lane >> 3) & 1))
                                       * LDS_STRIDE + kk + (lane >> 4) * 8) * 2;
                ldmx4(r, addr);
                bf[2 * ni2][0] = r[0]; bf[2 * ni2 + 1][0] = r[1];
                bf[2 * ni2][1] = r[2]; bf[2 * ni2 + 1][1] = r[3];
            }
#pragma unroll
            for (int mi = 0; mi < 2; mi++)
#pragma unroll
                for (int ni = 0; ni < 8; ni++)
                    mma16816h(acc[mi][ni], af[mi], bf[ni]);
        }

        if (c + 1 < NCH) {
            *(uint4*)(As[nxt] + r0 * LDS_STRIDE + c0) = pa0;
            *(uint4*)(As[nxt] + r1 * LDS_STRIDE + c0) = pa1;
            *(uint4*)(Bs[nxt] + r0 * LDS_STRIDE + c0) = pb0;
            *(uint4*)(Bs[nxt] + r1 * LDS_STRIDE + c0) = pb1;
        }
        __syncthreads();
    }

    // ---- epilogue ----
#pragma unroll
    for (int ni = 0; ni < 8; ni++) {
        const int n = n0 + warp_n + ni * 8 + (lane & 3) * 2;
        const float bv0 = __ldg(&bias[n]);
        const float bv1 = __ldg(&bias[n + 1]);
#pragma unroll
        for (int mi = 0; mi < 2; mi++) {
#pragma unroll
            for (int half = 0; half < 2; half++) {
                const int m = m0 + warp_m + mi * 16 + (lane >> 2) + half * 8;
                float ox = acc[mi][ni][2 * half] + bv0;
                float oy = acc[mi][ni][2 * half + 1] + bv1;
                if (MODE == 0) {
                    *(float2*)&C[(size_t)m * DMODEL + n] = make_float2(ox, oy);
                } else {
                    int b = m >> 11, s = m & 2047;
                    int h = n >> 6, d = n & 63;
                    if (MODE == 1) {
                        __half2 hv = __floats2half2_rn(ox, oy);
                        *(__half2*)&Ch[(((size_t)(b * 16 + h)) * S_LEN + s) * DK + d] = hv;
                    } else {
                        size_t vb = ((size_t)(b * 16 + h) * DK + d) * S_LEN + s;
                        Ch[vb] = __float2half(ox);
                        Ch[vb + S_LEN] = __float2half(oy);
                    }
                }
            }
        }
    }
}

// ==========================================================================
// HMMA fp16 fused causal attention.
// CTA: 128 q-rows, key tiles of 64. 8 warps, each owns 16 q-rows x all cols.
// Log2-domain online softmax with ex2.approx.f16x2; P kept as f16 in smem
// and consumed directly as the PV A-operand. ctx accumulated in registers.
// Writes unnormalized p~ to attn gmem (fixup normalizes later).
// ==========================================================================
#define ATT_STRIDE 72
#define ATT_SMEM ((128 * ATT_STRIDE + 64 * ATT_STRIDE + 64 * ATT_STRIDE + 128 * ATT_STRIDE) * 2)

__global__ __launch_bounds__(256, 1) void attn_hmma(
    const __half* __restrict__ qhf, const __half* __restrict__ khf,
    const __half* __restrict__ vtf,
    float* __restrict__ attn, float* __restrict__ ctx,
    float* __restrict__ gm, float* __restrict__ gl, float* __restrict__ gsnap)
{
    extern __shared__ __half sh[];
    __half* Qs = sh;                        // [128][72]
    __half* Ks = sh + 128 * ATT_STRIDE;     // [64][72]
    __half* Vt = Ks + 64 * ATT_STRIDE;      // [64][72]  rows=dk, cols=keys
    __half* Ps = Vt + 64 * ATT_STRIDE;      // [128][72]

    const int tid = threadIdx.x, lane = tid & 31, wid = tid >> 5;
    const int bh = blockIdx.x;
    const int qt = gridDim.y - 1 - blockIdx.y;   // large tiles scheduled first
    const int i0 = qt * 128;
    const int qw0 = wid * 16;
    const size_t qbase = (size_t)bh * S_LEN * DK;

    // load Q tile once: 128 x 64 f16 = 1024 uint4
#pragma unroll
    for (int it = 0; it < 4; it++) {
        int idx = tid + it * 256;
        int r = idx >> 3, g = idx & 7;
        *(uint4*)&Qs[r * ATT_STRIDE + g * 8] =
            *(const uint4*)&qhf[qbase + (size_t)(i0 + r) * DK + g * 8];
    }

    float m2[2] = {-1e30f, -1e30f};
    float l[2] = {0.f, 0.f};
    float cacc[8][4];
#pragma unroll
    for (int ni = 0; ni < 8; ni++)
#pragma unroll
        for (int j = 0; j < 4; j++) cacc[ni][j] = 0.f;

    const uint32_t sQ = smem_u32(Qs), sK = smem_u32(Ks);
    const uint32_t sV = smem_u32(Vt), sP = smem_u32(Ps);
    const int ntiles = 2 * qt + 2;
    const float SC = 0.18033688011112042f;  // log2(e) / sqrt(64)

    for (int jt = 0; jt < ntiles; jt++) {
        const int j0 = jt * 64;
        __syncthreads();
        // load K tile [64][64] + V^T tile [64 dk][64 keys]: 512 u4 each
#pragma unroll
        for (int it = 0; it < 2; it++) {
            int idx = tid + it * 256;
            int r = idx >> 3, g = idx & 7;
            *(uint4*)&Ks[r * ATT_STRIDE + g * 8] =
                *(const uint4*)&khf[qbase + (size_t)(j0 + r) * DK + g * 8];
            *(uint4*)&Vt[r * ATT_STRIDE + g * 8] =
                *(const uint4*)&vtf[((size_t)bh * DK + r) * S_LEN + j0 + g * 8];
        }
        __syncthreads();

        // ---- QK^T ----
        float sacc[8][4];
#pragma unroll
        for (int ni = 0; ni < 8; ni++)
#pragma unroll
            for (int j = 0; j < 4; j++) sacc[ni][j] = 0.f;

#pragma unroll
        for (int t = 0; t < 4; t++) {
            const int ko = t * 16;
            uint32_t af[4];
            ldmx4(af, sQ + ((qw0 + (lane & 15)) * ATT_STRIDE + ko + (lane >> 4) * 8) * 2);
            uint32_t bf[8][2];
#pragma unroll
            for (int nb = 0; nb < 4; nb++) {
                uint32_t r[4];
                ldmx4(r, sK + ((nb * 16 + (lane & 7) + 8 * ((lane >> 3) & 1)) * ATT_STRIDE
                               + ko + (lane >> 4) * 8) * 2);
                bf[2 * nb][0] = r[0]; bf[2 * nb + 1][0] = r[1];
                bf[2 * nb][1] = r[2]; bf[2 * nb + 1][1] = r[3];
            }
#pragma unroll
            for (int ni = 0; ni < 8; ni++) mma16816h(sacc[ni], af, bf[ni]);
        }

        // ---- scale to log2 domain + causal mask + row max ----
        float mx0 = -1e30f, mx1 = -1e30f;
        const bool masked = (jt >= ntiles - 2);
        const int rg0 = i0 + qw0 + (lane >> 2);
#pragma unroll
        for (int ni = 0; ni < 8; ni++) {
#pragma unroll
            for (int j = 0; j < 4; j++) sacc[ni][j] *= SC;
            if (masked) {
                int cg = j0 + ni * 8 + (lane & 3) * 2;
                if (cg > rg0)     sacc[ni][0] = -1e30f;
                if (cg + 1 > rg0) sacc[ni][1] = -1e30f;
                if (cg > rg0 + 8)     sacc[ni][2] = -1e30f;
                if (cg + 1 > rg0 + 8) sacc[ni][3] = -1e30f;
            }
            mx0 = fmaxf(mx0, fmaxf(sacc[ni][0], sacc[ni][1]));
            mx1 = fmaxf(mx1, fmaxf(sacc[ni][2], sacc[ni][3]));
        }
#pragma unroll
        for (int o = 1; o < 4; o <<= 1) {
            mx0 = fmaxf(mx0, __shfl_xor_sync(0xffffffffu, mx0, o));
            mx1 = fmaxf(mx1, __shfl_xor_sync(0xffffffffu, mx1, o));
        }
        const float mn0 = fmaxf(m2[0], mx0), mn1 = fmaxf(m2[1], mx1);
        const float esc0 = exp2f(m2[0] - mn0), esc1 = exp2f(m2[1] - mn1);
        m2[0] = mn0; m2[1] = mn1;

        // ---- p = exp2(s - m) via f16x2 MUFU; stash in Ps; sum l; write attn ----
        float ts0 = 0.f, ts1 = 0.f;
        const int prow0 = qw0 + (lane >> 2);
#pragma unroll
        for (int ni = 0; ni < 8; ni++) {
            const int c = ni * 8 + (lane & 3) * 2;
            uint32_t h0 = ex2_f16x2(pack_f16x2(sacc[ni][0] - mn0, sacc[ni][1] - mn0));
            uint32_t h1 = ex2_f16x2(pack_f16x2(sacc[ni][2] - mn1, sacc[ni][3] - mn1));
            *(uint32_t*)&Ps[prow0 * ATT_STRIDE + c] = h0;
            *(uint32_t*)&Ps[(prow0 + 8) * ATT_STRIDE + c] = h1;
            float2 f0 = __half22float2(*(__half2*)&h0);
            float2 f1 = __half22float2(*(__half2*)&h1);
            ts0 += f0.x + f0.y;
            ts1 += f1.x + f1.y;
            if (attn) {
                *(float2*)&attn[((size_t)bh * S_LEN + rg0) * S_LEN + j0 + c] = f0;
                *(float2*)&attn[((size_t)bh * S_LEN + rg0 + 8) * S_LEN + j0 + c] = f1;
            }
        }
#pragma unroll
        for (int o = 1; o < 4; o <<= 1) {
            ts0 += __shfl_xor_sync(0xffffffffu, ts0, o);
            ts1 += __shfl_xor_sync(0xffffffffu, ts1, o);
        }
        l[0] = l[0] * esc0 + ts0;
        l[1] = l[1] * esc1 + ts1;
#pragma unroll
        for (int ni = 0; ni < 8; ni++) {
            cacc[ni][0] *= esc0; cacc[ni][1] *= esc0;
            cacc[ni][2] *= esc1; cacc[ni][3] *= esc1;
        }
        if (attn && (lane & 3) == 0) {
            gsnap[((size_t)(bh * NTILE + jt)) * S_LEN + rg0] = m2[0];
            gsnap[((size_t)(bh * NTILE + jt)) * S_LEN + rg0 + 8] = m2[1];
        }
        __syncwarp();

        // ---- PV: ctx += P @ V ----
#pragma unroll
        for (int t = 0; t < 4; t++) {
            const int ko = t * 16;
            uint32_t af[4];
            ldmx4(af, sP + ((qw0 + (lane & 15)) * ATT_STRIDE + ko + (lane >> 4) * 8) * 2);
            uint32_t bf[8][2];
#pragma unroll
            for (int nb = 0; nb < 4; nb++) {
                uint32_t r[4];
                ldmx4(r, sV + ((nb * 16 + (lane & 7) + 8 * ((lane >> 3) & 1)) * ATT_STRIDE
                               + ko + (lane >> 4) * 8) * 2);
                bf[2 * nb][0] = r[0]; bf[2 * nb + 1][0] = r[1];
                bf[2 * nb][1] = r[2]; bf[2 * nb + 1][1] = r[3];
            }
#pragma unroll
            for (int ni = 0; ni < 8; ni++) mma16816h(cacc[ni], af, bf[ni]);
        }
    }

    // ---- epilogue ----
    const float li0 = 1.f / l[0], li1 = 1.f / l[1];
    const int r0 = i0 + qw0 + (lane >> 2), r1 = r0 + 8;
#pragma unroll
    for (int ni = 0; ni < 8; ni++) {
        const int d = ni * 8 + (lane & 3) * 2;
        *(float2*)&ctx[qbase + (size_t)r0 * DK + d] =
            make_float2(cacc[ni][0] * li0, cacc[ni][1] * li0);
        *(float2*)&ctx[qbase + (size_t)r1 * DK + d] =
            make_float2(cacc[ni][2] * li1, cacc[ni][3] * li1);
    }
    if ((lane & 3) == 0) {
        gm[bh * S_LEN + r0] = m2[0]; gm[bh * S_LEN + r1] = m2[1];
        gl[bh * S_LEN + r0] = l[0];  gl[bh * S_LEN + r1] = l[1];
    }
}

// ==========================================================================
// Fixup: attn = p~ * exp2(snap - m_fin) / l  (lower tri), 0 (upper tri).
// ==========================================================================
__global__ __launch_bounds__(256) void attn_fixup(
    const float* __restrict__ gm, const float* __restrict__ gl,
    const float* __restrict__ gsnap, float* __restrict__ attn)
{
    const int row = blockIdx.x;
    const int bh = row >> 11;
    const int i = row & 2047;
    const float mfin = gm[row];
    const float linv = 1.f / gl[row];
    const size_t rbase = (size_t)row * S_LEN;

#pragma unroll
    for (int t = 0; t < 2; t++) {
        int j4 = (threadIdx.x + t * 256) * 4;
        float4 o;
        if (j4 + 3 <= i) {
            int jt = j4 >> 6;
            float f = exp2f(gsnap[(size_t)(bh * NTILE + jt) * S_LEN + i] - mfin) * linv;
            float4 p = *(const float4*)&attn[rbase + j4];
            o = make_float4(p.x * f, p.y * f, p.z * f, p.w * f);
        } else if (j4 <= i) {
            int jt = j4 >> 6;
            float f = exp2f(gsnap[(size_t)(bh * NTILE + jt) * S_LEN + i] - mfin) * linv;
            float4 p = *(const float4*)&attn[rbase + j4];
            o.x = (j4 + 0 <= i) ? p.x * f : 0.f;
            o.y = (j4 + 1 <= i) ? p.y * f : 0.f;
            o.z = (j4 + 2 <= i) ? p.z * f : 0.f;
            o.w = (j4 + 3 <= i) ? p.w * f : 0.f;
        } else {
            o = make_float4(0.f, 0.f, 0.f, 0.f);
        }
        *(float4*)&attn[rbase + j4] = o;
    }
}

// ==========================================================================
// host launch
// ==========================================================================
extern "C" void kernel_launch(void* const* d_in, const int* in_sizes, int n_in,
                              void* d_out, int out_size)
{
    const float* q  = (const float*)d_in[0];
    const float* k  = (const float*)d_in[1];
    const float* v  = (const float*)d_in[2];
    const float* wq = (const float*)d_in[4];
    const float* bq = (const float*)d_in[5];
    const float* wk = (const float*)d_in[6];
    const float* bk = (const float*)d_in[7];
    const float* wv = (const float*)d_in[8];
    const float* bv = (const float*)d_in[9];
    const float* wo = (const float*)d_in[10];
    const float* bo = (const float*)d_in[11];

    float *ctx, *gm, *gl, *gsnap;
    __half *wh, *xh, *qhf, *khf, *vtf;
    cudaGetSymbolAddress((void**)&ctx, g_ctx);
    cudaGetSymbolAddress((void**)&gm, g_m);
    cudaGetSymbolAddress((void**)&gl, g_l);
    cudaGetSymbolAddress((void**)&gsnap, g_snap);
    cudaGetSymbolAddress((void**)&wh, g_wh);
    cudaGetSymbolAddress((void**)&xh, g_xh);
    cudaGetSymbolAddress((void**)&qhf, g_qhf);
    cudaGetSymbolAddress((void**)&khf, g_khf);
    cudaGetSymbolAddress((void**)&vtf, g_vtf);

    float* outbuf = (float*)d_out;
    float* out_ptr = nullptr;
    float* attn_ptr = nullptr;
    const long long OUT_N  = (long long)BATCH * S_LEN * DMODEL;
    const long long ATTN_N = (long long)BH * S_LEN * S_LEN;
    long long osz = (long long)out_size;
    if (osz >= OUT_N + ATTN_N)      { out_ptr = outbuf; attn_ptr = outbuf + OUT_N; }
    else if (osz == OUT_N)          { out_ptr = outbuf; }
    else                            { attn_ptr = outbuf; }

    cudaFuncSetAttribute(attn_hmma, cudaFuncAttributeMaxDynamicSharedMemorySize, ATT_SMEM);

    dim3 tgrid(32, 32);
    conv_w<<<tgrid, 256>>>(wq, wh + 0 * (size_t)DMODEL * DMODEL);
    conv_w<<<tgrid, 256>>>(wk, wh + 1 * (size_t)DMODEL * DMODEL);
    conv_w<<<tgrid, 256>>>(wv, wh + 2 * (size_t)DMODEL * DMODEL);
    conv_w<<<tgrid, 256>>>(wo, wh + 3 * (size_t)DMODEL * DMODEL);

    dim3 ggrid(DMODEL / 128, MROWS / 128);   // (8, 32)
    const int AGRID = MROWS * DMODEL / 256;  // 16384

    conv_a<false><<<AGRID, 256>>>(q, xh);
    gemm_hmma<1><<<ggrid, 256>>>(xh, wh + 0 * (size_t)DMODEL * DMODEL, bq, nullptr, qhf);
    conv_a<false><<<AGRID, 256>>>(k, xh);
    gemm_hmma<1><<<ggrid, 256>>>(xh, wh + 1 * (size_t)DMODEL * DMODEL, bk, nullptr, khf);
    conv_a<false><<<AGRID, 256>>>(v, xh);
    gemm_hmma<2><<<ggrid, 256>>>(xh, wh + 2 * (size_t)DMODEL * DMODEL, bv, nullptr, vtf);

    dim3 agrid(BH, S_LEN / 128);             // (32, 16)
    attn_hmma<<<agrid, 256, ATT_SMEM>>>(qhf, khf, vtf, attn_ptr, ctx, gm, gl, gsnap);

    if (attn_ptr) {
        attn_fixup<<<BH * S_LEN, 256>>>(gm, gl, gsnap, attn_ptr);
    }

    if (out_ptr) {
        conv_a<true><<<AGRID, 256>>>(ctx, xh);
        gemm_hmma<0><<<ggrid, 256>>>(xh, wh + 3 * (size_t)DMODEL * DMODEL, bo, out_ptr, nullptr);
    }
}

// round 7
// speedup vs baseline: 4.9590x; 1.1302x over previous
#include <cuda_runtime.h>
#include <cuda_fp16.h>
#include <cstdint>

#define S_LEN 2048
#define DMODEL 1024
#define NHEADS 16
#define DK 64
#define BATCH 2
#define BH (BATCH * NHEADS)
#define MROWS (BATCH * S_LEN)   // 4096
#define NTILE 32                // 2048/64 key tiles per row

// ---------------- scratch (device globals; no allocation allowed) ----------
__device__ float g_ctx[BH * S_LEN * DK];
__device__ float g_m[BH * S_LEN];           // log2-domain row max
__device__ float g_l[BH * S_LEN];           // row sumexp
__device__ __half g_wh[4 * DMODEL * DMODEL];    // weights [n][k] f16
__device__ __half g_xh[3 * MROWS * DMODEL];     // activations [m][k] f16 (q|k|v)
__device__ __half g_qhf[BH * S_LEN * DK];       // [bh][s][dk]
__device__ __half g_khf[BH * S_LEN * DK];       // [bh][s][dk]
__device__ __half g_vtf[BH * DK * S_LEN];       // [bh][dk][s]  (transposed)

// ---------------- primitives ------------------------------------------------
__device__ __forceinline__ uint32_t smem_u32(const void* p) {
    uint32_t a;
    asm("{ .reg .u64 t; cvta.to.shared.u64 t, %1; cvt.u32.u64 %0, t; }" : "=r"(a) : "l"(p));
    return a;
}
__device__ __forceinline__ void ldmx4(uint32_t* r, uint32_t addr) {
    asm volatile("ldmatrix.sync.aligned.m8n8.x4.shared.b16 {%0,%1,%2,%3}, [%4];"
                 : "=r"(r[0]), "=r"(r[1]), "=r"(r[2]), "=r"(r[3]) : "r"(addr));
}
__device__ __forceinline__ void mma16816h(float* c, const uint32_t* a, const uint32_t* b) {
    asm volatile(
        "mma.sync.aligned.m16n8k16.row.col.f32.f16.f16.f32 "
        "{%0,%1,%2,%3}, {%4,%5,%6,%7}, {%8,%9}, {%0,%1,%2,%3};"
        : "+f"(c[0]), "+f"(c[1]), "+f"(c[2]), "+f"(c[3])
        : "r"(a[0]), "r"(a[1]), "r"(a[2]), "r"(a[3]), "r"(b[0]), "r"(b[1]));
}
__device__ __forceinline__ uint32_t pack_f16x2(float lo, float hi) {
    uint32_t d;
    asm("cvt.rn.f16x2.f32 %0, %1, %2;" : "=r"(d) : "f"(hi), "f"(lo));
    return d;
}

// ==========================================================================
// Conversions
// ==========================================================================
__global__ __launch_bounds__(256) void conv_w4(
    const float* __restrict__ W0, const float* __restrict__ W1,
    const float* __restrict__ W2, const float* __restrict__ W3,
    __half* __restrict__ Wh)
{
    __shared__ float t[32][33];
    const int z = blockIdx.z;
    const float* W = (z == 0) ? W0 : (z == 1) ? W1 : (z == 2) ? W2 : W3;
    __half* dst = Wh + (size_t)z * DMODEL * DMODEL;
    const int bx = blockIdx.x * 32;   // n
    const int by = blockIdx.y * 32;   // k
    const int tx = threadIdx.x & 31;
    const int ty = threadIdx.x >> 5;
#pragma unroll
    for (int i = 0; i < 32; i += 8)
        t[ty + i][tx] = W[(size_t)(by + ty + i) * DMODEL + bx + tx];
    __syncthreads();
#pragma unroll
    for (int i = 0; i < 32; i += 8)
        dst[(size_t)(bx + ty + i) * DMODEL + by + tx] = __float2half(t[tx][ty + i]);
}

__global__ __launch_bounds__(256) void conv_qkv(
    const float* __restrict__ q, const float* __restrict__ k,
    const float* __restrict__ v, __half* __restrict__ Xh)
{
    const int z = blockIdx.y;
    const float* X = (z == 0) ? q : (z == 1) ? k : v;
    int idx = blockIdx.x * 256 + threadIdx.x;
    Xh[(size_t)z * MROWS * DMODEL + idx] = __float2half(X[idx]);
}

__global__ __launch_bounds__(256) void conv_ctx(
    const float* __restrict__ X, __half* __restrict__ Xh)
{
    int idx = blockIdx.x * 256 + threadIdx.x;
    int m = idx >> 10, kk = idx & 1023;
    int b = m >> 11, s = m & 2047, h = kk >> 6, d = kk & 63;
    Xh[idx] = __float2half(X[(((size_t)(b * 16 + h)) * S_LEN + s) * DK + d]);
}

// ==========================================================================
// HMMA fp16 GEMM mainloop (macro-style shared body via includes of logic)
// CTA 128x128, K-chunk 32, 256 threads (8 warps, 4m x 2n), warp tile 32x64.
// ==========================================================================
#define KC 32
#define NCH (DMODEL / KC)    // 32
#define LDS_STRIDE 40

#define GEMM_MAINLOOP(Arow, Brow)                                              \
    float acc[2][8][4];                                                        \
    _Pragma("unroll")                                                          \
    for (int mi = 0; mi < 2; mi++)                                             \
        _Pragma("unroll")                                                      \
        for (int ni = 0; ni < 8; ni++)                                         \
            _Pragma("unroll")                                                  \
            for (int j = 0; j < 4; j++) acc[mi][ni][j] = 0.f;                  \
    {                                                                          \
        uint4 a0 = *(const uint4*)(Arow + (size_t)r0 * DMODEL + c0);           \
        uint4 a1 = *(const uint4*)(Arow + (size_t)r1 * DMODEL + c0);           \
        uint4 b0 = *(const uint4*)(Brow + (size_t)r0 * DMODEL + c0);           \
        uint4 b1 = *(const uint4*)(Brow + (size_t)r1 * DMODEL + c0);           \
        *(uint4*)(As[0] + r0 * LDS_STRIDE + c0) = a0;                          \
        *(uint4*)(As[0] + r1 * LDS_STRIDE + c0) = a1;                          \
        *(uint4*)(Bs[0] + r0 * LDS_STRIDE + c0) = b0;                          \
        *(uint4*)(Bs[0] + r1 * LDS_STRIDE + c0) = b1;                          \
    }                                                                          \
    __syncthreads();                                                           \
    for (int c = 0; c < NCH; c++) {                                            \
        const int cur = c & 1, nxt = cur ^ 1;                                  \
        uint4 pa0, pa1, pb0, pb1;                                              \
        if (c + 1 < NCH) {                                                     \
            const int ko = (c + 1) * KC;                                       \
            pa0 = *(const uint4*)(Arow + (size_t)r0 * DMODEL + ko + c0);       \
            pa1 = *(const uint4*)(Arow + (size_t)r1 * DMODEL + ko + c0);       \
            pb0 = *(const uint4*)(Brow + (size_t)r0 * DMODEL + ko + c0);       \
            pb1 = *(const uint4*)(Brow + (size_t)r1 * DMODEL + ko + c0);       \
        }                                                                      \
        const uint32_t sa = smem_u32(As[cur]);                                 \
        const uint32_t sbm = smem_u32(Bs[cur]);                                \
        _Pragma("unroll")                                                      \
        for (int kk2 = 0; kk2 < 2; kk2++) {                                    \
            const int kk = kk2 * 16;                                           \
            uint32_t af[2][4];                                                 \
            _Pragma("unroll")                                                  \
            for (int mi = 0; mi < 2; mi++) {                                   \
                uint32_t addr = sa + ((warp_m + mi * 16 + (lane & 15)) * LDS_STRIDE \
                                      + kk + (lane >> 4) * 8) * 2;             \
                ldmx4(af[mi], addr);                                           \
            }                                                                  \
            uint32_t bf[8][2];                                                 \
            _Pragma("unroll")                                                  \
            for (int ni2 = 0; ni2 < 4; ni2++) {                                \
                uint32_t rr[4];                                                \
                uint32_t addr = sbm + ((warp_n + ni2 * 16 + (lane & 7) + 8 * ((lane >> 3) & 1)) \
                                       * LDS_STRIDE + kk + (lane >> 4) * 8) * 2; \
                ldmx4(rr, addr);                                               \
                bf[2 * ni2][0] = rr[0]; bf[2 * ni2 + 1][0] = rr[1];            \
                bf[2 * ni2][1] = rr[2]; bf[2 * ni2 + 1][1] = rr[3];            \
            }                                                                  \
            _Pragma("unroll")                                                  \
            for (int mi = 0; mi < 2; mi++)                                     \
                _Pragma("unroll")                                              \
                for (int ni = 0; ni < 8; ni++)                                 \
                    mma16816h(acc[mi][ni], af[mi], bf[ni]);                    \
        }                                                                      \
        if (c + 1 < NCH) {                                                     \
            *(uint4*)(As[nxt] + r0 * LDS_STRIDE + c0) = pa0;                   \
            *(uint4*)(As[nxt] + r1 * LDS_STRIDE + c0) = pa1;                   \
            *(uint4*)(Bs[nxt] + r0 * LDS_STRIDE + c0) = pb0;                   \
            *(uint4*)(Bs[nxt] + r1 * LDS_STRIDE + c0) = pb1;                   \
        }                                                                      \
        __syncthreads();                                                       \
    }

// QKV projections fused into one launch: grid.z selects q/k/v
__global__ __launch_bounds__(256) void gemm_qkv(
    const __half* __restrict__ Ah, const __half* __restrict__ Wh,
    const float* __restrict__ bq, const float* __restrict__ bk,
    const float* __restrict__ bv,
    __half* __restrict__ qhf, __half* __restrict__ khf, __half* __restrict__ vtf)
{
    __shared__ __half As[2][128 * LDS_STRIDE];
    __shared__ __half Bs[2][128 * LDS_STRIDE];

    const int tid = threadIdx.x;
    const int wid = tid >> 5, lane = tid & 31;
    const int z = blockIdx.z;
    const int m0 = blockIdx.y * 128, n0 = blockIdx.x * 128;
    const int warp_m = (wid & 3) * 32;
    const int warp_n = (wid >> 2) * 64;

    const __half* Arow = Ah + ((size_t)z * MROWS + m0) * DMODEL;
    const __half* Brow = Wh + ((size_t)z * DMODEL + n0) * DMODEL;
    const float* bias = (z == 0) ? bq : (z == 1) ? bk : bv;
    __half* Ch = (z == 0) ? qhf : (z == 1) ? khf : vtf;

    const int r0 = tid >> 2, c0 = (tid & 3) * 8;
    const int r1 = (tid + 256) >> 2;

    GEMM_MAINLOOP(Arow, Brow)

#pragma unroll
    for (int ni = 0; ni < 8; ni++) {
        const int n = n0 + warp_n + ni * 8 + (lane & 3) * 2;
        const float bv0 = __ldg(&bias[n]);
        const float bv1 = __ldg(&bias[n + 1]);
#pragma unroll
        for (int mi = 0; mi < 2; mi++) {
#pragma unroll
            for (int half = 0; half < 2; half++) {
                const int m = m0 + warp_m + mi * 16 + (lane >> 2) + half * 8;
                float ox = acc[mi][ni][2 * half] + bv0;
                float oy = acc[mi][ni][2 * half + 1] + bv1;
                int b = m >> 11, s = m & 2047;
                int h = n >> 6, d = n & 63;
                if (z < 2) {
                    *(__half2*)&Ch[(((size_t)(b * 16 + h)) * S_LEN + s) * DK + d] =
                        __floats2half2_rn(ox, oy);
                } else {
                    size_t vb = ((size_t)(b * 16 + h) * DK + d) * S_LEN + s;
                    Ch[vb] = __float2half(ox);
                    Ch[vb + S_LEN] = __float2half(oy);
                }
            }
        }
    }
}

// Output projection: fp32 C [m][1024]
__global__ __launch_bounds__(256) void gemm_out(
    const __half* __restrict__ Ah, const __half* __restrict__ Wh,
    const float* __restrict__ bias, float* __restrict__ C)
{
    __shared__ __half As[2][128 * LDS_STRIDE];
    __shared__ __half Bs[2][128 * LDS_STRIDE];

    const int tid = threadIdx.x;
    const int wid = tid >> 5, lane = tid & 31;
    const int m0 = blockIdx.y * 128, n0 = blockIdx.x * 128;
    const int warp_m = (wid & 3) * 32;
    const int warp_n = (wid >> 2) * 64;

    const __half* Arow = Ah + (size_t)m0 * DMODEL;
    const __half* Brow = Wh + (size_t)n0 * DMODEL;

    const int r0 = tid >> 2, c0 = (tid & 3) * 8;
    const int r1 = (tid + 256) >> 2;

    GEMM_MAINLOOP(Arow, Brow)

#pragma unroll
    for (int ni = 0; ni < 8; ni++) {
        const int n = n0 + warp_n + ni * 8 + (lane & 3) * 2;
        const float bv0 = __ldg(&bias[n]);
        const float bv1 = __ldg(&bias[n + 1]);
#pragma unroll
        for (int mi = 0; mi < 2; mi++) {
#pragma unroll
            for (int half = 0; half < 2; half++) {
                const int m = m0 + warp_m + mi * 16 + (lane >> 2) + half * 8;
                *(float2*)&C[(size_t)m * DMODEL + n] =
                    make_float2(acc[mi][ni][2 * half] + bv0,
                                acc[mi][ni][2 * half + 1] + bv1);
            }
        }
    }
}

// ==========================================================================
// Attention pass 1: per-row m (log2 domain) and l. QK only, flash-style.
// CTA: 128 q-rows; 8 warps x 16 rows. grid (BH, 16) y-reversed.
// ==========================================================================
#define ATT_STRIDE 72
#define SC_LOG2E 0.18033688011112042f   // log2(e)/sqrt(64)

__global__ __launch_bounds__(256, 1) void attn_pass1(
    const __half* __restrict__ qhf, const __half* __restrict__ khf,
    float* __restrict__ gm, float* __restrict__ gl)
{
    __shared__ __half Qs[128 * ATT_STRIDE];
    __shared__ __half Ks[64 * ATT_STRIDE];

    const int tid = threadIdx.x, lane = tid & 31, wid = tid >> 5;
    const int bh = blockIdx.x;
    const int qt = gridDim.y - 1 - blockIdx.y;
    const int i0 = qt * 128;
    const int qw0 = wid * 16;
    const size_t qbase = (size_t)bh * S_LEN * DK;

#pragma unroll
    for (int it = 0; it < 4; it++) {
        int idx = tid + it * 256;
        int r = idx >> 3, g = idx & 7;
        *(uint4*)&Qs[r * ATT_STRIDE + g * 8] =
            *(const uint4*)&qhf[qbase + (size_t)(i0 + r) * DK + g * 8];
    }

    float m2[2] = {-1e30f, -1e30f};
    float l[2] = {0.f, 0.f};
    const uint32_t sQ = smem_u32(Qs), sK = smem_u32(Ks);
    const int ntiles = 2 * qt + 2;
    const int rg0 = i0 + qw0 + (lane >> 2);

    for (int jt = 0; jt < ntiles; jt++) {
        const int j0 = jt * 64;
        __syncthreads();
#pragma unroll
        for (int it = 0; it < 2; it++) {
            int idx = tid + it * 256;
            int r = idx >> 3, g = idx & 7;
            *(uint4*)&Ks[r * ATT_STRIDE + g * 8] =
                *(const uint4*)&khf[qbase + (size_t)(j0 + r) * DK + g * 8];
        }
        __syncthreads();

        float sacc[8][4];
#pragma unroll
        for (int ni = 0; ni < 8; ni++)
#pragma unroll
            for (int j = 0; j < 4; j++) sacc[ni][j] = 0.f;

#pragma unroll
        for (int t = 0; t < 4; t++) {
            const int ko = t * 16;
            uint32_t af[4];
            ldmx4(af, sQ + ((qw0 + (lane & 15)) * ATT_STRIDE + ko + (lane >> 4) * 8) * 2);
            uint32_t bf[8][2];
#pragma unroll
            for (int nb = 0; nb < 4; nb++) {
                uint32_t r[4];
                ldmx4(r, sK + ((nb * 16 + (lane & 7) + 8 * ((lane >> 3) & 1)) * ATT_STRIDE
                               + ko + (lane >> 4) * 8) * 2);
                bf[2 * nb][0] = r[0]; bf[2 * nb + 1][0] = r[1];
                bf[2 * nb][1] = r[2]; bf[2 * nb + 1][1] = r[3];
            }
#pragma unroll
            for (int ni = 0; ni < 8; ni++) mma16816h(sacc[ni], af, bf[ni]);
        }

        float mx0 = -1e30f, mx1 = -1e30f;
        const bool masked = (jt >= ntiles - 2);
#pragma unroll
        for (int ni = 0; ni < 8; ni++) {
#pragma unroll
            for (int j = 0; j < 4; j++) sacc[ni][j] *= SC_LOG2E;
            if (masked) {
                int cg = j0 + ni * 8 + (lane & 3) * 2;
                if (cg > rg0)     sacc[ni][0] = -1e30f;
                if (cg + 1 > rg0) sacc[ni][1] = -1e30f;
                if (cg > rg0 + 8)     sacc[ni][2] = -1e30f;
                if (cg + 1 > rg0 + 8) sacc[ni][3] = -1e30f;
            }
            mx0 = fmaxf(mx0, fmaxf(sacc[ni][0], sacc[ni][1]));
            mx1 = fmaxf(mx1, fmaxf(sacc[ni][2], sacc[ni][3]));
        }
#pragma unroll
        for (int o = 1; o < 4; o <<= 1) {
            mx0 = fmaxf(mx0, __shfl_xor_sync(0xffffffffu, mx0, o));
            mx1 = fmaxf(mx1, __shfl_xor_sync(0xffffffffu, mx1, o));
        }
        const float mn0 = fmaxf(m2[0], mx0), mn1 = fmaxf(m2[1], mx1);
        float ts0 = 0.f, ts1 = 0.f;
#pragma unroll
        for (int ni = 0; ni < 8; ni++) {
            ts0 += exp2f(sacc[ni][0] - mn0) + exp2f(sacc[ni][1] - mn0);
            ts1 += exp2f(sacc[ni][2] - mn1) + exp2f(sacc[ni][3] - mn1);
        }
#pragma unroll
        for (int o = 1; o < 4; o <<= 1) {
            ts0 += __shfl_xor_sync(0xffffffffu, ts0, o);
            ts1 += __shfl_xor_sync(0xffffffffu, ts1, o);
        }
        l[0] = l[0] * exp2f(m2[0] - mn0) + ts0;
        l[1] = l[1] * exp2f(m2[1] - mn1) + ts1;
        m2[0] = mn0; m2[1] = mn1;
    }

    if ((lane & 3) == 0) {
        gm[bh * S_LEN + rg0] = m2[0];      gm[bh * S_LEN + rg0 + 8] = m2[1];
        gl[bh * S_LEN + rg0] = l[0];       gl[bh * S_LEN + rg0 + 8] = l[1];
    }
}

// ==========================================================================
// Attention pass 2: with m,l known, p = exp2(s-m) (fp32), attn = p/l written
// directly (normalized), PV via f16 P fragments, ctx = (P @ V)/l.
// No row reductions, no rescaling, no fixup.
// ==========================================================================
#define ATT2_SMEM ((128 * ATT_STRIDE + 64 * ATT_STRIDE + 64 * ATT_STRIDE + 128 * ATT_STRIDE) * 2)

__global__ __launch_bounds__(256, 1) void attn_pass2(
    const __half* __restrict__ qhf, const __half* __restrict__ khf,
    const __half* __restrict__ vtf,
    const float* __restrict__ gm, const float* __restrict__ gl,
    float* __restrict__ attn, float* __restrict__ ctx)
{
    extern __shared__ __half sh[];
    __half* Qs = sh;                        // [128][72]
    __half* Ks = sh + 128 * ATT_STRIDE;     // [64][72]
    __half* Vt = Ks + 64 * ATT_STRIDE;      // [64][72]
    __half* Ps = Vt + 64 * ATT_STRIDE;      // [128][72]

    const int tid = threadIdx.x, lane = tid & 31, wid = tid >> 5;
    const int bh = blockIdx.x;
    const int qt = gridDim.y - 1 - blockIdx.y;
    const int i0 = qt * 128;
    const int qw0 = wid * 16;
    const size_t qbase = (size_t)bh * S_LEN * DK;

#pragma unroll
    for (int it = 0; it < 4; it++) {
        int idx = tid + it * 256;
        int r = idx >> 3, g = idx & 7;
        *(uint4*)&Qs[r * ATT_STRIDE + g * 8] =
            *(const uint4*)&qhf[qbase + (size_t)(i0 + r) * DK + g * 8];
    }

    const int rg0 = i0 + qw0 + (lane >> 2);
    const float mf0 = gm[bh * S_LEN + rg0], mf1 = gm[bh * S_LEN + rg0 + 8];
    const float li0 = 1.f / gl[bh * S_LEN + rg0], li1 = 1.f / gl[bh * S_LEN + rg0 + 8];

    float cacc[8][4];
#pragma unroll
    for (int ni = 0; ni < 8; ni++)
#pragma unroll
        for (int j = 0; j < 4; j++) cacc[ni][j] = 0.f;

    const uint32_t sQ = smem_u32(Qs), sK = smem_u32(Ks);
    const uint32_t sV = smem_u32(Vt), sP = smem_u32(Ps);
    const int ntiles = 2 * qt + 2;

    for (int jt = 0; jt < ntiles; jt++) {
        const int j0 = jt * 64;
        __syncthreads();
#pragma unroll
        for (int it = 0; it < 2; it++) {
            int idx = tid + it * 256;
            int r = idx >> 3, g = idx & 7;
            *(uint4*)&Ks[r * ATT_STRIDE + g * 8] =
                *(const uint4*)&khf[qbase + (size_t)(j0 + r) * DK + g * 8];
            *(uint4*)&Vt[r * ATT_STRIDE + g * 8] =
                *(const uint4*)&vtf[((size_t)bh * DK + r) * S_LEN + j0 + g * 8];
        }
        __syncthreads();

        float sacc[8][4];
#pragma unroll
        for (int ni = 0; ni < 8; ni++)
#pragma unroll
            for (int j = 0; j < 4; j++) sacc[ni][j] = 0.f;

#pragma unroll
        for (int t = 0; t < 4; t++) {
            const int ko = t * 16;
            uint32_t af[4];
            ldmx4(af, sQ + ((qw0 + (lane & 15)) * ATT_STRIDE + ko + (lane >> 4) * 8) * 2);
            uint32_t bf[8][2];
#pragma unroll
            for (int nb = 0; nb < 4; nb++) {
                uint32_t r[4];
                ldmx4(r, sK + ((nb * 16 + (lane & 7) + 8 * ((lane >> 3) & 1)) * ATT_STRIDE
                               + ko + (lane >> 4) * 8) * 2);
                bf[2 * nb][0] = r[0]; bf[2 * nb + 1][0] = r[1];
                bf[2 * nb][1] = r[2]; bf[2 * nb + 1][1] = r[3];
            }
#pragma unroll
            for (int ni = 0; ni < 8; ni++) mma16816h(sacc[ni], af, bf[ni]);
        }

        const bool masked = (jt >= ntiles - 2);
        const int prow0 = qw0 + (lane >> 2);
#pragma unroll
        for (int ni = 0; ni < 8; ni++) {
            const int c = ni * 8 + (lane & 3) * 2;
            float s0 = sacc[ni][0] * SC_LOG2E, s1 = sacc[ni][1] * SC_LOG2E;
            float s2 = sacc[ni][2] * SC_LOG2E, s3 = sacc[ni][3] * SC_LOG2E;
            if (masked) {
                int cg = j0 + c;
                if (cg > rg0)         s0 = -1e30f;
                if (cg + 1 > rg0)     s1 = -1e30f;
                if (cg > rg0 + 8)     s2 = -1e30f;
                if (cg + 1 > rg0 + 8) s3 = -1e30f;
            }
            float p0 = exp2f(s0 - mf0), p1 = exp2f(s1 - mf0);
            float p2 = exp2f(s2 - mf1), p3 = exp2f(s3 - mf1);
            *(uint32_t*)&Ps[prow0 * ATT_STRIDE + c] = pack_f16x2(p0, p1);
            *(uint32_t*)&Ps[(prow0 + 8) * ATT_STRIDE + c] = pack_f16x2(p2, p3);
            if (attn) {
                *(float2*)&attn[((size_t)bh * S_LEN + rg0) * S_LEN + j0 + c] =
                    make_float2(p0 * li0, p1 * li0);
                *(float2*)&attn[((size_t)bh * S_LEN + rg0 + 8) * S_LEN + j0 + c] =
                    make_float2(p2 * li1, p3 * li1);
            }
        }
        __syncwarp();

#pragma unroll
        for (int t = 0; t < 4; t++) {
            const int ko = t * 16;
            uint32_t af[4];
            ldmx4(af, sP + ((qw0 + (lane & 15)) * ATT_STRIDE + ko + (lane >> 4) * 8) * 2);
            uint32_t bf[8][2];
#pragma unroll
            for (int nb = 0; nb < 4; nb++) {
                uint32_t r[4];
                ldmx4(r, sV + ((nb * 16 + (lane & 7) + 8 * ((lane >> 3) & 1)) * ATT_STRIDE
                               + ko + (lane >> 4) * 8) * 2);
                bf[2 * nb][0] = r[0]; bf[2 * nb + 1][0] = r[1];
                bf[2 * nb][1] = r[2]; bf[2 * nb + 1][1] = r[3];
            }
#pragma unroll
            for (int ni = 0; ni < 8; ni++) mma16816h(cacc[ni], af, bf[ni]);
        }
    }

    // zero-fill the never-visited upper-triangle tiles of attn
    if (attn) {
        for (int jt = ntiles; jt < NTILE; jt++) {
            const int j0 = jt * 64;
#pragma unroll
            for (int it = 0; it < 8; it++) {
                int idx = tid + it * 256;          // 0..2047 float4 slots
                int r = idx >> 4, c4 = (idx & 15) << 2;
                *(float4*)&attn[((size_t)bh * S_LEN + i0 + r) * S_LEN + j0 + c4] =
                    make_float4(0.f, 0.f, 0.f, 0.f);
            }
        }
    }

    // epilogue: ctx = cacc / l
#pragma unroll
    for (int ni = 0; ni < 8; ni++) {
        const int d = ni * 8 + (lane & 3) * 2;
        *(float2*)&ctx[qbase + (size_t)rg0 * DK + d] =
            make_float2(cacc[ni][0] * li0, cacc[ni][1] * li0);
        *(float2*)&ctx[qbase + (size_t)(rg0 + 8) * DK + d] =
            make_float2(cacc[ni][2] * li1, cacc[ni][3] * li1);
    }
}

// ==========================================================================
// host launch
// ==========================================================================
extern "C" void kernel_launch(void* const* d_in, const int* in_sizes, int n_in,
                              void* d_out, int out_size)
{
    const float* q  = (const float*)d_in[0];
    const float* k  = (const float*)d_in[1];
    const float* v  = (const float*)d_in[2];
    const float* wq = (const float*)d_in[4];
    const float* bq = (const float*)d_in[5];
    const float* wk = (const float*)d_in[6];
    const float* bk = (const float*)d_in[7];
    const float* wv = (const float*)d_in[8];
    const float* bv = (const float*)d_in[9];
    const float* wo = (const float*)d_in[10];
    const float* bo = (const float*)d_in[11];

    float *ctx, *gm, *gl;
    __half *wh, *xh, *qhf, *khf, *vtf;
    cudaGetSymbolAddress((void**)&ctx, g_ctx);
    cudaGetSymbolAddress((void**)&gm, g_m);
    cudaGetSymbolAddress((void**)&gl, g_l);
    cudaGetSymbolAddress((void**)&wh, g_wh);
    cudaGetSymbolAddress((void**)&xh, g_xh);
    cudaGetSymbolAddress((void**)&qhf, g_qhf);
    cudaGetSymbolAddress((void**)&khf, g_khf);
    cudaGetSymbolAddress((void**)&vtf, g_vtf);

    float* outbuf = (float*)d_out;
    float* out_ptr = nullptr;
    float* attn_ptr = nullptr;
    const long long OUT_N  = (long long)BATCH * S_LEN * DMODEL;
    const long long ATTN_N = (long long)BH * S_LEN * S_LEN;
    long long osz = (long long)out_size;
    if (osz >= OUT_N + ATTN_N)      { out_ptr = outbuf; attn_ptr = outbuf + OUT_N; }
    else if (osz == OUT_N)          { out_ptr = outbuf; }
    else                            { attn_ptr = outbuf; }

    cudaFuncSetAttribute(attn_pass2, cudaFuncAttributeMaxDynamicSharedMemorySize, ATT2_SMEM);

    dim3 wgrid(32, 32, 4);
    conv_w4<<<wgrid, 256>>>(wq, wk, wv, wo, wh);

    dim3 cgrid(MROWS * DMODEL / 256, 3);
    conv_qkv<<<cgrid, 256>>>(q, k, v, xh);

    dim3 ggrid(DMODEL / 128, MROWS / 128, 3);   // (8, 32, 3)
    gemm_qkv<<<ggrid, 256>>>(xh, wh, bq, bk, bv, qhf, khf, vtf);

    dim3 agrid(BH, S_LEN / 128);                // (32, 16)
    attn_pass1<<<agrid, 256>>>(qhf, khf, gm, gl);
    attn_pass2<<<agrid, 256, ATT2_SMEM>>>(qhf, khf, vtf, gm, gl, attn_ptr, ctx);

    if (out_ptr) {
        conv_ctx<<<MROWS * DMODEL / 256, 256>>>(ctx, xh);
        dim3 ogrid(DMODEL / 128, MROWS / 128);
        gemm_out<<<ogrid, 256>>>(xh, wh + 3 * (size_t)DMODEL * DMODEL, bo, out_ptr);
    }
}